// round 11
// baseline (speedup 1.0000x reference)
#include <cuda_runtime.h>
#include <cuda_fp16.h>
#include <cstdint>

#define B_   2
#define T_   2048
#define DM   1024
#define H_   16
#define HD   64
#define ROWS (B_ * T_)        // 4096

// ---------------- scratch (no cudaMalloc allowed) ----------------
__device__ __half g_xh[ROWS * DM];
__device__ __half g_wh[4 * DM * DM];   // Wq, Wk, Wv, Wo (fp16)
__device__ __half g_qh[ROWS * DM];
__device__ __half g_kh[ROWS * DM];
__device__ __half g_vh[ROWS * DM];
__device__ __half g_ah[ROWS * DM];

// =================================================================
// low-level helpers
// =================================================================
__device__ __forceinline__ uint32_t smem_u32(const void* p) {
    uint32_t a;
    asm("{ .reg .u64 t; cvta.to.shared.u64 t, %1; cvt.u32.u64 %0, t; }"
        : "=r"(a) : "l"(p));
    return a;
}
__device__ __forceinline__ void cp16(uint32_t dst, const void* src) {
    asm volatile("cp.async.cg.shared.global [%0], [%1], 16;" :: "r"(dst), "l"(src));
}
#define CP_COMMIT() asm volatile("cp.async.commit_group;")

__device__ __forceinline__ void ldsm4(uint32_t (&r)[4], uint32_t addr) {
    asm volatile("ldmatrix.sync.aligned.m8n8.x4.shared.b16 {%0,%1,%2,%3}, [%4];"
                 : "=r"(r[0]), "=r"(r[1]), "=r"(r[2]), "=r"(r[3]) : "r"(addr));
}
__device__ __forceinline__ void ldsm4t(uint32_t (&r)[4], uint32_t addr) {
    asm volatile("ldmatrix.sync.aligned.m8n8.x4.trans.shared.b16 {%0,%1,%2,%3}, [%4];"
                 : "=r"(r[0]), "=r"(r[1]), "=r"(r[2]), "=r"(r[3]) : "r"(addr));
}
__device__ __forceinline__ void mma_f16(float (&d)[4], const uint32_t (&a)[4],
                                        uint32_t b0, uint32_t b1) {
    asm volatile(
        "mma.sync.aligned.m16n8k16.row.col.f32.f16.f16.f32 "
        "{%0,%1,%2,%3}, {%4,%5,%6,%7}, {%8,%9}, {%0,%1,%2,%3};"
        : "+f"(d[0]), "+f"(d[1]), "+f"(d[2]), "+f"(d[3])
        : "r"(a[0]), "r"(a[1]), "r"(a[2]), "r"(a[3]), "r"(b0), "r"(b1));
}
__device__ __forceinline__ float ex2(float x) {
    float y;
    asm("ex2.approx.ftz.f32 %0, %1;" : "=f"(y) : "f"(x));
    return y;
}
__device__ __forceinline__ uint32_t h2pack(float c0, float c1) {
    uint32_t r;
    asm("cvt.rn.f16x2.f32 %0, %1, %2;" : "=r"(r) : "f"(c1), "f"(c0));
    return r;
}
__device__ __forceinline__ uint32_t swz(int r, int c) {
    return (uint32_t)(r * 128 + ((c ^ (r & 7)) << 4));
}

// =================================================================
// single fused fp32 -> fp16 convert: x (1M float4) + 4 W (256K each)
// =================================================================
#define NX4 (ROWS * DM / 4)   // 1048576
#define NW4 (DM * DM / 4)     // 262144

__global__ void __launch_bounds__(256)
conv_all(const float* __restrict__ x,
         const float* __restrict__ w0, const float* __restrict__ w1,
         const float* __restrict__ w2, const float* __restrict__ w3,
         __half* __restrict__ xh, __half* __restrict__ wh)
{
    int i = blockIdx.x * blockDim.x + threadIdx.x;
    const float* src;
    __half* dst;
    int off;
    if (i < NX4) {
        src = x; dst = xh; off = i;
    } else {
        int j = i - NX4;
        int w = j >> 18;
        off = j & (NW4 - 1);
        src = (w == 0) ? w0 : (w == 1) ? w1 : (w == 2) ? w2 : w3;
        dst = wh + (size_t)w * DM * DM;
    }
    float4 v = ((const float4*)src)[off];
    uint2 o;
    o.x = h2pack(v.x, v.y);
    o.y = h2pack(v.z, v.w);
    ((uint2*)dst)[off] = o;
}

// =================================================================
// fp16 HMMA GEMM: CTA 128x128, 4 warps of m64n64, BK=64,
// 2-stage single-sync pipeline, single-buffered frags,
// <=170 regs -> 3 CTAs/SM (12 warps/SM).
// =================================================================
#define GBK      64
#define NKC      (DM / GBK)     // 16
#define TILE_B   (128 * 128)    // 16 KB per 128x64-fp16 tile
#define STAGE_B  (2 * TILE_B)   // A tile + W tile
#define GEMM_SMEM (2 * STAGE_B) // 64 KB

__device__ __forceinline__ void load_tile128(uint32_t dst, const __half* g,
                                             int row0, int k0, int tid) {
    const char* gb = (const char*)(g + (size_t)row0 * DM + k0);
#pragma unroll
    for (int it = 0; it < 8; it++) {
        int idx = tid + it * 128;
        int r = idx >> 3;
        int c = idx & 7;
        cp16(dst + swz(r, c), gb + (size_t)r * DM * 2 + c * 16);
    }
}

template<int MODE>
__device__ __forceinline__ void hgemm_body(
    const __half* __restrict__ A, const __half* __restrict__ W,
    float* __restrict__ Cf, __half* __restrict__ Ch,
    int m0, int n0, uint32_t sb)
{
    const int tid = threadIdx.x;
    const int wid = tid >> 5;
    const int lane = tid & 31;
    const int wm = wid >> 1;
    const int wn = wid & 1;
    const int lrow = lane & 15;
    const int lsel = lane >> 4;

    float acc[4][8][4];
#pragma unroll
    for (int i = 0; i < 4; i++)
#pragma unroll
        for (int j = 0; j < 8; j++)
#pragma unroll
            for (int e = 0; e < 4; e++) acc[i][j][e] = 0.f;

    auto stage = [&](int s) { return sb + s * STAGE_B; };

    // prologue: chunk 0 -> stage 0
    load_tile128(stage(0) + 0 * TILE_B, A, m0, 0, tid);
    load_tile128(stage(0) + 1 * TILE_B, W, n0, 0, tid);
    CP_COMMIT();

    for (int kc = 0; kc < NKC; kc++) {
        asm volatile("cp.async.wait_group 0;");
        __syncthreads();   // publishes chunk kc; readers of stage (kc+1)&1 done

        if (kc + 1 < NKC) {
            int s2 = (kc + 1) & 1;
            int k0 = (kc + 1) * GBK;
            load_tile128(stage(s2) + 0 * TILE_B, A, m0, k0, tid);
            load_tile128(stage(s2) + 1 * TILE_B, W, n0, k0, tid);
            CP_COMMIT();
        }

        const uint32_t sA = stage(kc & 1) + 0 * TILE_B;
        const uint32_t sW = stage(kc & 1) + 1 * TILE_B;

#pragma unroll
        for (int t = 0; t < 4; t++) {
            const int c0 = t * 2;
            uint32_t af[4][4], bf[4][4];
#pragma unroll
            for (int mf = 0; mf < 4; mf++) {
                int r = wm * 64 + mf * 16 + lrow;
                ldsm4(af[mf], sA + (uint32_t)(r * 128 + (((c0 + lsel) ^ (r & 7)) << 4)));
            }
#pragma unroll
            for (int nf = 0; nf < 4; nf++) {
                int r = wn * 64 + nf * 16 + lrow;
                ldsm4(bf[nf], sW + (uint32_t)(r * 128 + (((c0 + lsel) ^ (r & 7)) << 4)));
            }
#pragma unroll
            for (int mf = 0; mf < 4; mf++) {
#pragma unroll
                for (int nf = 0; nf < 4; nf++) {
                    mma_f16(acc[mf][2 * nf],     af[mf], bf[nf][0], bf[nf][2]);
                    mma_f16(acc[mf][2 * nf + 1], af[mf], bf[nf][1], bf[nf][3]);
                }
            }
        }
    }

    const int erow = m0 + wm * 64 + (lane >> 2);
    const int ecol = n0 + wn * 64 + (lane & 3) * 2;
#pragma unroll
    for (int mf = 0; mf < 4; mf++) {
#pragma unroll
        for (int nf = 0; nf < 8; nf++) {
            size_t o0 = (size_t)(erow + mf * 16) * DM + ecol + nf * 8;
            if (MODE == 0) {
                *(float2*)(Cf + o0) = make_float2(acc[mf][nf][0], acc[mf][nf][1]);
                *(float2*)(Cf + o0 + 8 * DM) = make_float2(acc[mf][nf][2], acc[mf][nf][3]);
            } else {
                *(uint32_t*)(Ch + o0) = h2pack(acc[mf][nf][0], acc[mf][nf][1]);
                *(uint32_t*)(Ch + o0 + 8 * DM) = h2pack(acc[mf][nf][2], acc[mf][nf][3]);
            }
        }
    }
}

__global__ void __launch_bounds__(128, 3)
hgemm_qkv(const __half* __restrict__ A, const __half* __restrict__ Wall,
          __half* __restrict__ q, __half* __restrict__ k, __half* __restrict__ v)
{
    extern __shared__ char smraw[];
    const int wsel = blockIdx.x >> 3;
    const int n0 = (blockIdx.x & 7) * 128;
    const int m0 = blockIdx.y * 128;
    const __half* W = Wall + (size_t)wsel * DM * DM;
    __half* Ch = (wsel == 0) ? q : (wsel == 1) ? k : v;
    hgemm_body<1>(A, W, nullptr, Ch, m0, n0, smem_u32(smraw));
}

__global__ void __launch_bounds__(128, 3)
hgemm_o(const __half* __restrict__ A, const __half* __restrict__ W,
        float* __restrict__ Cf)
{
    extern __shared__ char smraw[];
    hgemm_body<0>(A, W, Cf, nullptr, blockIdx.y * 128, blockIdx.x * 128,
                  smem_u32(smraw));
}

// =================================================================
// FlashAttention-2 style causal ALiBi attention (R9 exact body).
// smem: Q 16KB + 2 stages x (K 8KB + V 8KB) = 48KB.
// =================================================================
#define AT_Q 128
#define AT_K 64
#define ATT_SMEM (16384 + 32768)

__device__ __forceinline__ void load_kv(uint32_t base,
        const __half* kh, const __half* vh, int b, int h, int kb, int tid)
{
    size_t grow = (size_t)(b * T_ + kb * AT_K) * DM + h * HD;
#pragma unroll
    for (int t = 0; t < 2; t++) {
        int idx = tid + t * 256;
        int r = idx >> 3;
        int c = idx & 7;
        uint32_t sw = swz(r, c);
        size_t off = grow + (size_t)r * DM;
        cp16(base +        sw, (const char*)(kh + off) + c * 16);
        cp16(base + 8192 + sw, (const char*)(vh + off) + c * 16);
    }
}

__global__ void __launch_bounds__(256)
attn_mma(const __half* __restrict__ qh, const __half* __restrict__ kh,
         const __half* __restrict__ vh, __half* __restrict__ oh)
{
    extern __shared__ char smraw[];
    const uint32_t sb = smem_u32(smraw);
    const int tid = threadIdx.x, w = tid >> 5, lane = tid & 31;
    const int h = blockIdx.y, b = blockIdx.z;
    const int i0 = (gridDim.x - 1 - blockIdx.x) * AT_Q;
    const int lrow = lane & 15, lsel = lane >> 4;
    const int rq = lane >> 2, c2 = (lane & 3) * 2;
    const int irow_base = i0 + w * 16;
    const int irow = irow_base + rq;

    const float slope  = ex2(-0.5f * (float)(h + 1));
    const float slope2 = slope * 1.4426950408889634f;
    const float scale2 = 0.18033688011112042f;

    const uint32_t sQ = sb;
    auto stgK = [&](int s) { return sb + 16384 + s * 16384; };

    {
        const char* gq = (const char*)(qh + (size_t)(b * T_ + i0) * DM + h * HD);
#pragma unroll
        for (int t = 0; t < 4; t++) {
            int idx = tid + t * 256;
            int r = idx >> 3;
            int c = idx & 7;
            cp16(sQ + swz(r, c), gq + (size_t)r * DM * 2 + c * 16);
        }
        load_kv(stgK(0), kh, vh, b, h, 0, tid);
        CP_COMMIT();
    }

    uint32_t qf[4][4];
    float O[8][4];
#pragma unroll
    for (int i = 0; i < 8; i++)
#pragma unroll
        for (int e = 0; e < 4; e++) O[i][e] = 0.f;
    float m0 = -1e30f, m1 = -1e30f, l0 = 0.f, l1 = 0.f;

    const int NB = (i0 + AT_Q) / AT_K;

    for (int kb = 0; kb < NB; kb++) {
        int s = kb & 1;
        if (kb + 1 < NB) {
            load_kv(stgK(s ^ 1), kh, vh, b, h, kb + 1, tid);
            CP_COMMIT();
            asm volatile("cp.async.wait_group 1;");
        } else {
            asm volatile("cp.async.wait_group 0;");
        }
        __syncthreads();

        if (kb == 0) {
#pragma unroll
            for (int ks = 0; ks < 4; ks++) {
                int r = w * 16 + lrow;
                uint32_t off = (uint32_t)(r * 128 + (((2 * ks + lsel) ^ (r & 7)) << 4));
                ldsm4(qf[ks], sQ + off);
            }
        }

        if (kb * AT_K <= irow_base + 15) {
            const uint32_t sK = stgK(s), sV = sK + 8192;

            float S[8][4];
#pragma unroll
            for (int i = 0; i < 8; i++)
#pragma unroll
                for (int e = 0; e < 4; e++) S[i][e] = 0.f;

#pragma unroll
            for (int ks = 0; ks < 4; ks++) {
#pragma unroll
                for (int np = 0; np < 4; np++) {
                    int r = np * 16 + lrow;
                    uint32_t off = (uint32_t)(r * 128 + (((2 * ks + lsel) ^ (r & 7)) << 4));
                    uint32_t bh[4];
                    ldsm4(bh, sK + off);
                    mma_f16(S[2 * np],     qf[ks], bh[0], bh[2]);
                    mma_f16(S[2 * np + 1], qf[ks], bh[1], bh[3]);
                }
            }

            const int jb = kb * AT_K + c2;
            const bool nomask = (kb * AT_K + 63) <= irow_base;
            float rm0 = -1e30f, rm1 = -1e30f;
#pragma unroll
            for (int nf = 0; nf < 8; nf++) {
                int d0 = irow - (jb + 8 * nf);
                float fd = (float)d0;
                float bia = -slope2 * fd;
                float t0 = fmaf(S[nf][0], scale2, bia);
                float t1 = fmaf(S[nf][1], scale2, bia + slope2);
                float t2 = fmaf(S[nf][2], scale2, bia - 8.f * slope2);
                float t3 = fmaf(S[nf][3], scale2, bia - 7.f * slope2);
                if (!nomask) {
                    t0 = (d0 >= 0)  ? t0 : -1e30f;
                    t1 = (d0 >= 1)  ? t1 : -1e30f;
                    t2 = (d0 >= -8) ? t2 : -1e30f;
                    t3 = (d0 >= -7) ? t3 : -1e30f;
                }
                S[nf][0] = t0; S[nf][1] = t1; S[nf][2] = t2; S[nf][3] = t3;
                rm0 = fmaxf(rm0, fmaxf(t0, t1));
                rm1 = fmaxf(rm1, fmaxf(t2, t3));
            }
            rm0 = fmaxf(rm0, __shfl_xor_sync(0xffffffffu, rm0, 1));
            rm0 = fmaxf(rm0, __shfl_xor_sync(0xffffffffu, rm0, 2));
            rm1 = fmaxf(rm1, __shfl_xor_sync(0xffffffffu, rm1, 1));
            rm1 = fmaxf(rm1, __shfl_xor_sync(0xffffffffu, rm1, 2));

            float m0n = fmaxf(m0, rm0), m1n = fmaxf(m1, rm1);
            float cr0 = ex2(m0 - m0n), cr1 = ex2(m1 - m1n);
            m0 = m0n; m1 = m1n;
            l0 *= cr0; l1 *= cr1;
#pragma unroll
            for (int nf = 0; nf < 8; nf++) {
                O[nf][0] *= cr0; O[nf][1] *= cr0;
                O[nf][2] *= cr1; O[nf][3] *= cr1;
            }
#pragma unroll
            for (int nf = 0; nf < 8; nf++) {
                float p0 = ex2(S[nf][0] - m0);
                float p1 = ex2(S[nf][1] - m0);
                float p2 = ex2(S[nf][2] - m1);
                float p3 = ex2(S[nf][3] - m1);
                S[nf][0] = p0; S[nf][1] = p1; S[nf][2] = p2; S[nf][3] = p3;
                l0 += p0 + p1;
                l1 += p2 + p3;
            }

#pragma unroll
            for (int ks2 = 0; ks2 < 4; ks2++) {
                uint32_t af2[4];
                af2[0] = h2pack(S[2 * ks2][0],     S[2 * ks2][1]);
                af2[1] = h2pack(S[2 * ks2][2],     S[2 * ks2][3]);
                af2[2] = h2pack(S[2 * ks2 + 1][0], S[2 * ks2 + 1][1]);
                af2[3] = h2pack(S[2 * ks2 + 1][2], S[2 * ks2 + 1][3]);
#pragma unroll
                for (int nf2 = 0; nf2 < 4; nf2++) {
                    int r = ks2 * 16 + lrow;
                    uint32_t off = (uint32_t)(r * 128 + (((2 * nf2 + lsel) ^ (r & 7)) << 4));
                    uint32_t bh[4];
                    ldsm4t(bh, sV + off);
                    mma_f16(O[2 * nf2],     af2, bh[0], bh[1]);
                    mma_f16(O[2 * nf2 + 1], af2, bh[2], bh[3]);
                }
            }
        }
        __syncthreads();
    }

    l0 += __shfl_xor_sync(0xffffffffu, l0, 1);
    l0 += __shfl_xor_sync(0xffffffffu, l0, 2);
    l1 += __shfl_xor_sync(0xffffffffu, l1, 1);
    l1 += __shfl_xor_sync(0xffffffffu, l1, 2);
    float iv0 = 1.0f / l0, iv1 = 1.0f / l1;

    size_t obase = (size_t)(b * T_ + irow) * DM + h * HD + c2;
#pragma unroll
    for (int nf = 0; nf < 8; nf++) {
        *(uint32_t*)(oh + obase + 8 * nf) =
            h2pack(O[nf][0] * iv0, O[nf][1] * iv0);
        *(uint32_t*)(oh + obase + 8 * DM + 8 * nf) =
            h2pack(O[nf][2] * iv1, O[nf][3] * iv1);
    }
}

// =================================================================
extern "C" void kernel_launch(void* const* d_in, const int* in_sizes, int n_in,
                              void* d_out, int out_size)
{
    const float* x  = (const float*)d_in[0];
    const float* Wq = (const float*)d_in[1];
    const float* Wk = (const float*)d_in[2];
    const float* Wv = (const float*)d_in[3];
    const float* Wo = (const float*)d_in[4];
    float* out = (float*)d_out;

    __half *xh, *wh, *qh, *kh, *vh, *ah;
    cudaGetSymbolAddress((void**)&xh, g_xh);
    cudaGetSymbolAddress((void**)&wh, g_wh);
    cudaGetSymbolAddress((void**)&qh, g_qh);
    cudaGetSymbolAddress((void**)&kh, g_kh);
    cudaGetSymbolAddress((void**)&vh, g_vh);
    cudaGetSymbolAddress((void**)&ah, g_ah);

    cudaFuncSetAttribute(hgemm_qkv,
                         cudaFuncAttributeMaxDynamicSharedMemorySize, GEMM_SMEM);
    cudaFuncSetAttribute(hgemm_o,
                         cudaFuncAttributeMaxDynamicSharedMemorySize, GEMM_SMEM);
    cudaFuncSetAttribute(attn_mma,
                         cudaFuncAttributeMaxDynamicSharedMemorySize, ATT_SMEM);

    conv_all<<<(NX4 + 4 * NW4) / 256, 256>>>(x, Wq, Wk, Wv, Wo, xh, wh);

    hgemm_qkv<<<dim3(24, ROWS / 128), 128, GEMM_SMEM>>>(xh, wh, qh, kh, vh);

    dim3 agrid(T_ / AT_Q, H_, B_);      // (16, 16, 2)
    attn_mma<<<agrid, 256, ATT_SMEM>>>(qh, kh, vh, ah);

    hgemm_o<<<dim3(DM / 128, ROWS / 128), 128, GEMM_SMEM>>>(
        ah, wh + 3 * (size_t)DM * DM, out);
}

// round 12
// speedup vs baseline: 1.0329x; 1.0329x over previous
#include <cuda_runtime.h>
#include <cuda_fp16.h>
#include <cstdint>

#define B_   2
#define T_   2048
#define DM   1024
#define H_   16
#define HD   64
#define ROWS (B_ * T_)        // 4096

// ---------------- scratch (no cudaMalloc allowed) ----------------
__device__ __half g_xh[ROWS * DM];
__device__ __half g_wh[4 * DM * DM];   // Wq, Wk, Wv, Wo (fp16)
__device__ __half g_qh[ROWS * DM];
__device__ __half g_kh[ROWS * DM];
__device__ __half g_vh[ROWS * DM];
__device__ __half g_ah[ROWS * DM];

// =================================================================
// low-level helpers
// =================================================================
__device__ __forceinline__ uint32_t smem_u32(const void* p) {
    uint32_t a;
    asm("{ .reg .u64 t; cvta.to.shared.u64 t, %1; cvt.u32.u64 %0, t; }"
        : "=r"(a) : "l"(p));
    return a;
}
__device__ __forceinline__ void cp16(uint32_t dst, const void* src) {
    asm volatile("cp.async.cg.shared.global [%0], [%1], 16;" :: "r"(dst), "l"(src));
}
#define CP_COMMIT() asm volatile("cp.async.commit_group;")

__device__ __forceinline__ void ldsm4(uint32_t (&r)[4], uint32_t addr) {
    asm volatile("ldmatrix.sync.aligned.m8n8.x4.shared.b16 {%0,%1,%2,%3}, [%4];"
                 : "=r"(r[0]), "=r"(r[1]), "=r"(r[2]), "=r"(r[3]) : "r"(addr));
}
__device__ __forceinline__ void ldsm4t(uint32_t (&r)[4], uint32_t addr) {
    asm volatile("ldmatrix.sync.aligned.m8n8.x4.trans.shared.b16 {%0,%1,%2,%3}, [%4];"
                 : "=r"(r[0]), "=r"(r[1]), "=r"(r[2]), "=r"(r[3]) : "r"(addr));
}
__device__ __forceinline__ void mma_f16(float (&d)[4], const uint32_t (&a)[4],
                                        uint32_t b0, uint32_t b1) {
    asm volatile(
        "mma.sync.aligned.m16n8k16.row.col.f32.f16.f16.f32 "
        "{%0,%1,%2,%3}, {%4,%5,%6,%7}, {%8,%9}, {%0,%1,%2,%3};"
        : "+f"(d[0]), "+f"(d[1]), "+f"(d[2]), "+f"(d[3])
        : "r"(a[0]), "r"(a[1]), "r"(a[2]), "r"(a[3]), "r"(b0), "r"(b1));
}
__device__ __forceinline__ float ex2(float x) {
    float y;
    asm("ex2.approx.ftz.f32 %0, %1;" : "=f"(y) : "f"(x));
    return y;
}
__device__ __forceinline__ uint32_t h2pack(float c0, float c1) {
    uint32_t r;
    asm("cvt.rn.f16x2.f32 %0, %1, %2;" : "=r"(r) : "f"(c1), "f"(c0));
    return r;
}
__device__ __forceinline__ uint32_t swz(int r, int c) {
    return (uint32_t)(r * 128 + ((c ^ (r & 7)) << 4));
}

// =================================================================
// single fused fp32 -> fp16 convert: x (1M float4) + 4 W (256K each)
// =================================================================
#define NX4 (ROWS * DM / 4)   // 1048576
#define NW4 (DM * DM / 4)     // 262144

__global__ void __launch_bounds__(256)
conv_all(const float* __restrict__ x,
         const float* __restrict__ w0, const float* __restrict__ w1,
         const float* __restrict__ w2, const float* __restrict__ w3,
         __half* __restrict__ xh, __half* __restrict__ wh)
{
    int i = blockIdx.x * blockDim.x + threadIdx.x;
    const float* src;
    __half* dst;
    int off;
    if (i < NX4) {
        src = x; dst = xh; off = i;
    } else {
        int j = i - NX4;
        int w = j >> 18;
        off = j & (NW4 - 1);
        src = (w == 0) ? w0 : (w == 1) ? w1 : (w == 2) ? w2 : w3;
        dst = wh + (size_t)w * DM * DM;
    }
    float4 v = ((const float4*)src)[off];
    uint2 o;
    o.x = h2pack(v.x, v.y);
    o.y = h2pack(v.z, v.w);
    ((uint2*)dst)[off] = o;
}

// =================================================================
// fp16 HMMA GEMM (R9 exact): CTA 128x128, 4 warps m64n64, BK=64,
// 3-stage single-sync pipeline + register frag double buffer.
// =================================================================
#define GBK      64
#define NKC      (DM / GBK)     // 16
#define TILE_B   (128 * 128)    // 16 KB per 128x64-fp16 tile
#define STAGE_B  (2 * TILE_B)   // A tile + W tile
#define GEMM_SMEM (3 * STAGE_B) // 96 KB

__device__ __forceinline__ void load_tile128(uint32_t dst, const __half* g,
                                             int row0, int k0, int tid) {
    const char* gb = (const char*)(g + (size_t)row0 * DM + k0);
#pragma unroll
    for (int it = 0; it < 8; it++) {
        int idx = tid + it * 128;
        int r = idx >> 3;
        int c = idx & 7;
        cp16(dst + swz(r, c), gb + (size_t)r * DM * 2 + c * 16);
    }
}

template<int MODE>
__device__ __forceinline__ void hgemm_body(
    const __half* __restrict__ A, const __half* __restrict__ W,
    float* __restrict__ Cf, __half* __restrict__ Ch,
    int m0, int n0, uint32_t sb)
{
    const int tid = threadIdx.x;
    const int wid = tid >> 5;
    const int lane = tid & 31;
    const int wm = wid >> 1;
    const int wn = wid & 1;
    const int lrow = lane & 15;
    const int lsel = lane >> 4;

    int arow[4], brow[4];
#pragma unroll
    for (int mf = 0; mf < 4; mf++) arow[mf] = wm * 64 + mf * 16 + lrow;
#pragma unroll
    for (int nf = 0; nf < 4; nf++) brow[nf] = wn * 64 + nf * 16 + lrow;

    float acc[4][8][4];
#pragma unroll
    for (int i = 0; i < 4; i++)
#pragma unroll
        for (int j = 0; j < 8; j++)
#pragma unroll
            for (int e = 0; e < 4; e++) acc[i][j][e] = 0.f;

    auto stage = [&](int s) { return sb + s * STAGE_B; };

    load_tile128(stage(0) + 0 * TILE_B, A, m0, 0, tid);
    load_tile128(stage(0) + 1 * TILE_B, W, n0, 0, tid);
    CP_COMMIT();
    load_tile128(stage(1) + 0 * TILE_B, A, m0, GBK, tid);
    load_tile128(stage(1) + 1 * TILE_B, W, n0, GBK, tid);
    CP_COMMIT();

    uint32_t af[2][4][4], bf[2][4][4];

    for (int kc = 0; kc < NKC; kc++) {
        if (kc + 1 < NKC) {
            asm volatile("cp.async.wait_group 1;");
        } else {
            asm volatile("cp.async.wait_group 0;");
        }
        __syncthreads();

        if (kc + 2 < NKC) {
            int s2 = (kc + 2) % 3;
            int k0 = (kc + 2) * GBK;
            load_tile128(stage(s2) + 0 * TILE_B, A, m0, k0, tid);
            load_tile128(stage(s2) + 1 * TILE_B, W, n0, k0, tid);
            CP_COMMIT();
        }

        const uint32_t sA = stage(kc % 3) + 0 * TILE_B;
        const uint32_t sW = stage(kc % 3) + 1 * TILE_B;

        auto ldfrags = [&](int buf, int t) {
            const int c0 = t * 2;
#pragma unroll
            for (int mf = 0; mf < 4; mf++) {
                int r = arow[mf];
                ldsm4(af[buf][mf], sA + (uint32_t)(r * 128 + (((c0 + lsel) ^ (r & 7)) << 4)));
            }
#pragma unroll
            for (int nf = 0; nf < 4; nf++) {
                int r = brow[nf];
                ldsm4(bf[buf][nf], sW + (uint32_t)(r * 128 + (((c0 + lsel) ^ (r & 7)) << 4)));
            }
        };

        ldfrags(0, 0);
#pragma unroll
        for (int t = 0; t < 4; t++) {
            if (t < 3) ldfrags((t + 1) & 1, t + 1);
            const int cb = t & 1;
#pragma unroll
            for (int mf = 0; mf < 4; mf++) {
#pragma unroll
                for (int nf = 0; nf < 4; nf++) {
                    mma_f16(acc[mf][2 * nf],     af[cb][mf], bf[cb][nf][0], bf[cb][nf][2]);
                    mma_f16(acc[mf][2 * nf + 1], af[cb][mf], bf[cb][nf][1], bf[cb][nf][3]);
                }
            }
        }
    }

    const int erow = m0 + wm * 64 + (lane >> 2);
    const int ecol = n0 + wn * 64 + (lane & 3) * 2;
#pragma unroll
    for (int mf = 0; mf < 4; mf++) {
#pragma unroll
        for (int nf = 0; nf < 8; nf++) {
            size_t o0 = (size_t)(erow + mf * 16) * DM + ecol + nf * 8;
            if (MODE == 0) {
                *(float2*)(Cf + o0) = make_float2(acc[mf][nf][0], acc[mf][nf][1]);
                *(float2*)(Cf + o0 + 8 * DM) = make_float2(acc[mf][nf][2], acc[mf][nf][3]);
            } else {
                *(uint32_t*)(Ch + o0) = h2pack(acc[mf][nf][0], acc[mf][nf][1]);
                *(uint32_t*)(Ch + o0 + 8 * DM) = h2pack(acc[mf][nf][2], acc[mf][nf][3]);
            }
        }
    }
}

__global__ void __launch_bounds__(128, 2)
hgemm_qkv(const __half* __restrict__ A, const __half* __restrict__ Wall,
          __half* __restrict__ q, __half* __restrict__ k, __half* __restrict__ v)
{
    extern __shared__ char smraw[];
    const int wsel = blockIdx.x >> 3;
    const int n0 = (blockIdx.x & 7) * 128;
    const int m0 = blockIdx.y * 128;
    const __half* W = Wall + (size_t)wsel * DM * DM;
    __half* Ch = (wsel == 0) ? q : (wsel == 1) ? k : v;
    hgemm_body<1>(A, W, nullptr, Ch, m0, n0, smem_u32(smraw));
}

__global__ void __launch_bounds__(128, 2)
hgemm_o(const __half* __restrict__ A, const __half* __restrict__ W,
        float* __restrict__ Cf)
{
    extern __shared__ char smraw[];
    hgemm_body<0>(A, W, Cf, nullptr, blockIdx.y * 128, blockIdx.x * 128,
                  smem_u32(smraw));
}

// =================================================================
// FlashAttention-2 style causal ALiBi attention, fp16 HMMA.
// K/V staged in 128-key blocks (2 stages, 80 KB smem); compute in
// two 64-key sub-blocks with arithmetic identical to R9.
// =================================================================
#define AT_Q 128
#define AT_KB 128                        // staged keys per block
#define KV_B  (AT_KB * 128 * 2)          // 32 KB per stage (K 16K + V 16K)
#define ATT_SMEM (16384 + 2 * KV_B)      // 80 KB

__device__ __forceinline__ void load_kv128(uint32_t base,
        const __half* kh, const __half* vh, int b, int h, int kb, int tid)
{
    size_t grow = (size_t)(b * T_ + kb * AT_KB) * DM + h * HD;
#pragma unroll
    for (int t = 0; t < 4; t++) {
        int idx = tid + t * 256;         // 1024 -> 128 rows x 8 chunks
        int r = idx >> 3;
        int c = idx & 7;
        uint32_t sw = swz(r, c);
        size_t off = grow + (size_t)r * DM;
        cp16(base +         sw, (const char*)(kh + off) + c * 16);
        cp16(base + 16384 + sw, (const char*)(vh + off) + c * 16);
    }
}

__global__ void __launch_bounds__(256)
attn_mma(const __half* __restrict__ qh, const __half* __restrict__ kh,
         const __half* __restrict__ vh, __half* __restrict__ oh)
{
    extern __shared__ char smraw[];
    const uint32_t sb = smem_u32(smraw);
    const int tid = threadIdx.x, w = tid >> 5, lane = tid & 31;
    const int h = blockIdx.y, b = blockIdx.z;
    const int i0 = (gridDim.x - 1 - blockIdx.x) * AT_Q;
    const int lrow = lane & 15, lsel = lane >> 4;
    const int rq = lane >> 2, c2 = (lane & 3) * 2;
    const int irow_base = i0 + w * 16;
    const int irow = irow_base + rq;

    const float slope  = ex2(-0.5f * (float)(h + 1));
    const float slope2 = slope * 1.4426950408889634f;
    const float scale2 = 0.18033688011112042f;

    const uint32_t sQ = sb;
    auto stgK = [&](int s) { return sb + 16384 + s * KV_B; };

    {
        const char* gq = (const char*)(qh + (size_t)(b * T_ + i0) * DM + h * HD);
#pragma unroll
        for (int t = 0; t < 4; t++) {
            int idx = tid + t * 256;
            int r = idx >> 3;
            int c = idx & 7;
            cp16(sQ + swz(r, c), gq + (size_t)r * DM * 2 + c * 16);
        }
        load_kv128(stgK(0), kh, vh, b, h, 0, tid);
        CP_COMMIT();
    }

    uint32_t qf[4][4];
    float O[8][4];
#pragma unroll
    for (int i = 0; i < 8; i++)
#pragma unroll
        for (int e = 0; e < 4; e++) O[i][e] = 0.f;
    float m0 = -1e30f, m1 = -1e30f, l0 = 0.f, l1 = 0.f;

    const int NB = (i0 + AT_Q) / AT_KB;   // 128-key blocks (>=1)

    for (int kb = 0; kb < NB; kb++) {
        int s = kb & 1;
        if (kb + 1 < NB) {
            load_kv128(stgK(s ^ 1), kh, vh, b, h, kb + 1, tid);
            CP_COMMIT();
            asm volatile("cp.async.wait_group 1;");
        } else {
            asm volatile("cp.async.wait_group 0;");
        }
        __syncthreads();

        if (kb == 0) {
#pragma unroll
            for (int ks = 0; ks < 4; ks++) {
                int r = w * 16 + lrow;
                uint32_t off = (uint32_t)(r * 128 + (((2 * ks + lsel) ^ (r & 7)) << 4));
                ldsm4(qf[ks], sQ + off);
            }
        }

        // two 64-key sub-blocks; arithmetic identical to the 64-key version
#pragma unroll
        for (int sub = 0; sub < 2; sub++) {
            const int j0 = kb * AT_KB + sub * 64;
            if (j0 > irow_base + 15) continue;   // warp-uniform causal skip

            const uint32_t sK = stgK(s) + sub * 8192;
            const uint32_t sV = stgK(s) + 16384 + sub * 8192;

            float S[8][4];
#pragma unroll
            for (int i = 0; i < 8; i++)
#pragma unroll
                for (int e = 0; e < 4; e++) S[i][e] = 0.f;

#pragma unroll
            for (int ks = 0; ks < 4; ks++) {
#pragma unroll
                for (int np = 0; np < 4; np++) {
                    int r = np * 16 + lrow;
                    uint32_t off = (uint32_t)(r * 128 + (((2 * ks + lsel) ^ (r & 7)) << 4));
                    uint32_t bh[4];
                    ldsm4(bh, sK + off);
                    mma_f16(S[2 * np],     qf[ks], bh[0], bh[2]);
                    mma_f16(S[2 * np + 1], qf[ks], bh[1], bh[3]);
                }
            }

            const int jb = j0 + c2;
            const bool nomask = (j0 + 63) <= irow_base;
            float rm0 = -1e30f, rm1 = -1e30f;
#pragma unroll
            for (int nf = 0; nf < 8; nf++) {
                int d0 = irow - (jb + 8 * nf);
                float fd = (float)d0;
                float bia = -slope2 * fd;
                float t0 = fmaf(S[nf][0], scale2, bia);
                float t1 = fmaf(S[nf][1], scale2, bia + slope2);
                float t2 = fmaf(S[nf][2], scale2, bia - 8.f * slope2);
                float t3 = fmaf(S[nf][3], scale2, bia - 7.f * slope2);
                if (!nomask) {
                    t0 = (d0 >= 0)  ? t0 : -1e30f;
                    t1 = (d0 >= 1)  ? t1 : -1e30f;
                    t2 = (d0 >= -8) ? t2 : -1e30f;
                    t3 = (d0 >= -7) ? t3 : -1e30f;
                }
                S[nf][0] = t0; S[nf][1] = t1; S[nf][2] = t2; S[nf][3] = t3;
                rm0 = fmaxf(rm0, fmaxf(t0, t1));
                rm1 = fmaxf(rm1, fmaxf(t2, t3));
            }
            rm0 = fmaxf(rm0, __shfl_xor_sync(0xffffffffu, rm0, 1));
            rm0 = fmaxf(rm0, __shfl_xor_sync(0xffffffffu, rm0, 2));
            rm1 = fmaxf(rm1, __shfl_xor_sync(0xffffffffu, rm1, 1));
            rm1 = fmaxf(rm1, __shfl_xor_sync(0xffffffffu, rm1, 2));

            float m0n = fmaxf(m0, rm0), m1n = fmaxf(m1, rm1);
            float cr0 = ex2(m0 - m0n), cr1 = ex2(m1 - m1n);
            m0 = m0n; m1 = m1n;
            l0 *= cr0; l1 *= cr1;
#pragma unroll
            for (int nf = 0; nf < 8; nf++) {
                O[nf][0] *= cr0; O[nf][1] *= cr0;
                O[nf][2] *= cr1; O[nf][3] *= cr1;
            }
#pragma unroll
            for (int nf = 0; nf < 8; nf++) {
                float p0 = ex2(S[nf][0] - m0);
                float p1 = ex2(S[nf][1] - m0);
                float p2 = ex2(S[nf][2] - m1);
                float p3 = ex2(S[nf][3] - m1);
                S[nf][0] = p0; S[nf][1] = p1; S[nf][2] = p2; S[nf][3] = p3;
                l0 += p0 + p1;
                l1 += p2 + p3;
            }

#pragma unroll
            for (int ks2 = 0; ks2 < 4; ks2++) {
                uint32_t af2[4];
                af2[0] = h2pack(S[2 * ks2][0],     S[2 * ks2][1]);
                af2[1] = h2pack(S[2 * ks2][2],     S[2 * ks2][3]);
                af2[2] = h2pack(S[2 * ks2 + 1][0], S[2 * ks2 + 1][1]);
                af2[3] = h2pack(S[2 * ks2 + 1][2], S[2 * ks2 + 1][3]);
#pragma unroll
                for (int nf2 = 0; nf2 < 4; nf2++) {
                    int r = ks2 * 16 + lrow;
                    uint32_t off = (uint32_t)(r * 128 + (((2 * nf2 + lsel) ^ (r & 7)) << 4));
                    uint32_t bh[4];
                    ldsm4t(bh, sV + off);
                    mma_f16(O[2 * nf2],     af2, bh[0], bh[1]);
                    mma_f16(O[2 * nf2 + 1], af2, bh[2], bh[3]);
                }
            }
        }
        __syncthreads();
    }

    l0 += __shfl_xor_sync(0xffffffffu, l0, 1);
    l0 += __shfl_xor_sync(0xffffffffu, l0, 2);
    l1 += __shfl_xor_sync(0xffffffffu, l1, 1);
    l1 += __shfl_xor_sync(0xffffffffu, l1, 2);
    float iv0 = 1.0f / l0, iv1 = 1.0f / l1;

    size_t obase = (size_t)(b * T_ + irow) * DM + h * HD + c2;
#pragma unroll
    for (int nf = 0; nf < 8; nf++) {
        *(uint32_t*)(oh + obase + 8 * nf) =
            h2pack(O[nf][0] * iv0, O[nf][1] * iv0);
        *(uint32_t*)(oh + obase + 8 * DM + 8 * nf) =
            h2pack(O[nf][2] * iv1, O[nf][3] * iv1);
    }
}

// =================================================================
extern "C" void kernel_launch(void* const* d_in, const int* in_sizes, int n_in,
                              void* d_out, int out_size)
{
    const float* x  = (const float*)d_in[0];
    const float* Wq = (const float*)d_in[1];
    const float* Wk = (const float*)d_in[2];
    const float* Wv = (const float*)d_in[3];
    const float* Wo = (const float*)d_in[4];
    float* out = (float*)d_out;

    __half *xh, *wh, *qh, *kh, *vh, *ah;
    cudaGetSymbolAddress((void**)&xh, g_xh);
    cudaGetSymbolAddress((void**)&wh, g_wh);
    cudaGetSymbolAddress((void**)&qh, g_qh);
    cudaGetSymbolAddress((void**)&kh, g_kh);
    cudaGetSymbolAddress((void**)&vh, g_vh);
    cudaGetSymbolAddress((void**)&ah, g_ah);

    cudaFuncSetAttribute(hgemm_qkv,
                         cudaFuncAttributeMaxDynamicSharedMemorySize, GEMM_SMEM);
    cudaFuncSetAttribute(hgemm_o,
                         cudaFuncAttributeMaxDynamicSharedMemorySize, GEMM_SMEM);
    cudaFuncSetAttribute(attn_mma,
                         cudaFuncAttributeMaxDynamicSharedMemorySize, ATT_SMEM);

    conv_all<<<(NX4 + 4 * NW4) / 256, 256>>>(x, Wq, Wk, Wv, Wo, xh, wh);

    hgemm_qkv<<<dim3(24, ROWS / 128), 128, GEMM_SMEM>>>(xh, wh, qh, kh, vh);

    dim3 agrid(T_ / AT_Q, H_, B_);      // (16, 16, 2)
    attn_mma<<<agrid, 256, ATT_SMEM>>>(qh, kh, vh, ah);

    hgemm_o<<<dim3(DM / 128, ROWS / 128), 128, GEMM_SMEM>>>(
        ah, wh + 3 * (size_t)DM * DM, out);
}

// round 13
// speedup vs baseline: 1.0374x; 1.0044x over previous
#include <cuda_runtime.h>
#include <cuda_fp16.h>
#include <cstdint>

#define B_   2
#define T_   2048
#define DM   1024
#define H_   16
#define HD   64
#define ROWS (B_ * T_)        // 4096

// ---------------- scratch (no cudaMalloc allowed) ----------------
__device__ __half g_xh[ROWS * DM];
__device__ __half g_wh[4 * DM * DM];   // Wq, Wk, Wv, Wo (fp16)
__device__ __half g_qh[ROWS * DM];
__device__ __half g_kh[ROWS * DM];
__device__ __half g_vh[ROWS * DM];
__device__ __half g_ah[ROWS * DM];

// =================================================================
// low-level helpers
// =================================================================
__device__ __forceinline__ uint32_t smem_u32(const void* p) {
    uint32_t a;
    asm("{ .reg .u64 t; cvta.to.shared.u64 t, %1; cvt.u32.u64 %0, t; }"
        : "=r"(a) : "l"(p));
    return a;
}
__device__ __forceinline__ void cp16(uint32_t dst, const void* src) {
    asm volatile("cp.async.cg.shared.global [%0], [%1], 16;" :: "r"(dst), "l"(src));
}
#define CP_COMMIT() asm volatile("cp.async.commit_group;")

__device__ __forceinline__ void ldsm4(uint32_t (&r)[4], uint32_t addr) {
    asm volatile("ldmatrix.sync.aligned.m8n8.x4.shared.b16 {%0,%1,%2,%3}, [%4];"
                 : "=r"(r[0]), "=r"(r[1]), "=r"(r[2]), "=r"(r[3]) : "r"(addr));
}
__device__ __forceinline__ void ldsm4t(uint32_t (&r)[4], uint32_t addr) {
    asm volatile("ldmatrix.sync.aligned.m8n8.x4.trans.shared.b16 {%0,%1,%2,%3}, [%4];"
                 : "=r"(r[0]), "=r"(r[1]), "=r"(r[2]), "=r"(r[3]) : "r"(addr));
}
__device__ __forceinline__ void mma_f16(float (&d)[4], const uint32_t (&a)[4],
                                        uint32_t b0, uint32_t b1) {
    asm volatile(
        "mma.sync.aligned.m16n8k16.row.col.f32.f16.f16.f32 "
        "{%0,%1,%2,%3}, {%4,%5,%6,%7}, {%8,%9}, {%0,%1,%2,%3};"
        : "+f"(d[0]), "+f"(d[1]), "+f"(d[2]), "+f"(d[3])
        : "r"(a[0]), "r"(a[1]), "r"(a[2]), "r"(a[3]), "r"(b0), "r"(b1));
}
// fp16-accumulate variant (half-rate-f32-accum hypothesis test)
__device__ __forceinline__ void mma_f16acc(uint32_t (&d)[2], const uint32_t (&a)[4],
                                           uint32_t b0, uint32_t b1) {
    asm volatile(
        "mma.sync.aligned.m16n8k16.row.col.f16.f16.f16.f16 "
        "{%0,%1}, {%2,%3,%4,%5}, {%6,%7}, {%0,%1};"
        : "+r"(d[0]), "+r"(d[1])
        : "r"(a[0]), "r"(a[1]), "r"(a[2]), "r"(a[3]), "r"(b0), "r"(b1));
}
__device__ __forceinline__ float ex2(float x) {
    float y;
    asm("ex2.approx.ftz.f32 %0, %1;" : "=f"(y) : "f"(x));
    return y;
}
__device__ __forceinline__ uint32_t h2pack(float c0, float c1) {
    uint32_t r;
    asm("cvt.rn.f16x2.f32 %0, %1, %2;" : "=r"(r) : "f"(c1), "f"(c0));
    return r;
}
__device__ __forceinline__ float2 h2unpack(uint32_t v) {
    __half2 h = *reinterpret_cast<__half2*>(&v);
    return __half22float2(h);
}
__device__ __forceinline__ uint32_t swz(int r, int c) {
    return (uint32_t)(r * 128 + ((c ^ (r & 7)) << 4));
}

// =================================================================
// single fused fp32 -> fp16 convert: x (1M float4) + 4 W (256K each)
// =================================================================
#define NX4 (ROWS * DM / 4)   // 1048576
#define NW4 (DM * DM / 4)     // 262144

__global__ void __launch_bounds__(256)
conv_all(const float* __restrict__ x,
         const float* __restrict__ w0, const float* __restrict__ w1,
         const float* __restrict__ w2, const float* __restrict__ w3,
         __half* __restrict__ xh, __half* __restrict__ wh)
{
    int i = blockIdx.x * blockDim.x + threadIdx.x;
    const float* src;
    __half* dst;
    int off;
    if (i < NX4) {
        src = x; dst = xh; off = i;
    } else {
        int j = i - NX4;
        int w = j >> 18;
        off = j & (NW4 - 1);
        src = (w == 0) ? w0 : (w == 1) ? w1 : (w == 2) ? w2 : w3;
        dst = wh + (size_t)w * DM * DM;
    }
    float4 v = ((const float4*)src)[off];
    uint2 o;
    o.x = h2pack(v.x, v.y);
    o.y = h2pack(v.z, v.w);
    ((uint2*)dst)[off] = o;
}

// =================================================================
// fp16 HMMA GEMM (R9 exact): CTA 128x128, 4 warps m64n64, BK=64,
// 3-stage single-sync pipeline + register frag double buffer.
// =================================================================
#define GBK      64
#define NKC      (DM / GBK)     // 16
#define TILE_B   (128 * 128)    // 16 KB per 128x64-fp16 tile
#define STAGE_B  (2 * TILE_B)   // A tile + W tile
#define GEMM_SMEM (3 * STAGE_B) // 96 KB

__device__ __forceinline__ void load_tile128(uint32_t dst, const __half* g,
                                             int row0, int k0, int tid) {
    const char* gb = (const char*)(g + (size_t)row0 * DM + k0);
#pragma unroll
    for (int it = 0; it < 8; it++) {
        int idx = tid + it * 128;
        int r = idx >> 3;
        int c = idx & 7;
        cp16(dst + swz(r, c), gb + (size_t)r * DM * 2 + c * 16);
    }
}

template<int MODE>
__device__ __forceinline__ void hgemm_body(
    const __half* __restrict__ A, const __half* __restrict__ W,
    float* __restrict__ Cf, __half* __restrict__ Ch,
    int m0, int n0, uint32_t sb)
{
    const int tid = threadIdx.x;
    const int wid = tid >> 5;
    const int lane = tid & 31;
    const int wm = wid >> 1;
    const int wn = wid & 1;
    const int lrow = lane & 15;
    const int lsel = lane >> 4;

    int arow[4], brow[4];
#pragma unroll
    for (int mf = 0; mf < 4; mf++) arow[mf] = wm * 64 + mf * 16 + lrow;
#pragma unroll
    for (int nf = 0; nf < 4; nf++) brow[nf] = wn * 64 + nf * 16 + lrow;

    float acc[4][8][4];
#pragma unroll
    for (int i = 0; i < 4; i++)
#pragma unroll
        for (int j = 0; j < 8; j++)
#pragma unroll
            for (int e = 0; e < 4; e++) acc[i][j][e] = 0.f;

    auto stage = [&](int s) { return sb + s * STAGE_B; };

    load_tile128(stage(0) + 0 * TILE_B, A, m0, 0, tid);
    load_tile128(stage(0) + 1 * TILE_B, W, n0, 0, tid);
    CP_COMMIT();
    load_tile128(stage(1) + 0 * TILE_B, A, m0, GBK, tid);
    load_tile128(stage(1) + 1 * TILE_B, W, n0, GBK, tid);
    CP_COMMIT();

    uint32_t af[2][4][4], bf[2][4][4];

    for (int kc = 0; kc < NKC; kc++) {
        if (kc + 1 < NKC) {
            asm volatile("cp.async.wait_group 1;");
        } else {
            asm volatile("cp.async.wait_group 0;");
        }
        __syncthreads();

        if (kc + 2 < NKC) {
            int s2 = (kc + 2) % 3;
            int k0 = (kc + 2) * GBK;
            load_tile128(stage(s2) + 0 * TILE_B, A, m0, k0, tid);
            load_tile128(stage(s2) + 1 * TILE_B, W, n0, k0, tid);
            CP_COMMIT();
        }

        const uint32_t sA = stage(kc % 3) + 0 * TILE_B;
        const uint32_t sW = stage(kc % 3) + 1 * TILE_B;

        auto ldfrags = [&](int buf, int t) {
            const int c0 = t * 2;
#pragma unroll
            for (int mf = 0; mf < 4; mf++) {
                int r = arow[mf];
                ldsm4(af[buf][mf], sA + (uint32_t)(r * 128 + (((c0 + lsel) ^ (r & 7)) << 4)));
            }
#pragma unroll
            for (int nf = 0; nf < 4; nf++) {
                int r = brow[nf];
                ldsm4(bf[buf][nf], sW + (uint32_t)(r * 128 + (((c0 + lsel) ^ (r & 7)) << 4)));
            }
        };

        ldfrags(0, 0);
#pragma unroll
        for (int t = 0; t < 4; t++) {
            if (t < 3) ldfrags((t + 1) & 1, t + 1);
            const int cb = t & 1;
#pragma unroll
            for (int mf = 0; mf < 4; mf++) {
#pragma unroll
                for (int nf = 0; nf < 4; nf++) {
                    mma_f16(acc[mf][2 * nf],     af[cb][mf], bf[cb][nf][0], bf[cb][nf][2]);
                    mma_f16(acc[mf][2 * nf + 1], af[cb][mf], bf[cb][nf][1], bf[cb][nf][3]);
                }
            }
        }
    }

    const int erow = m0 + wm * 64 + (lane >> 2);
    const int ecol = n0 + wn * 64 + (lane & 3) * 2;
#pragma unroll
    for (int mf = 0; mf < 4; mf++) {
#pragma unroll
        for (int nf = 0; nf < 8; nf++) {
            size_t o0 = (size_t)(erow + mf * 16) * DM + ecol + nf * 8;
            if (MODE == 0) {
                *(float2*)(Cf + o0) = make_float2(acc[mf][nf][0], acc[mf][nf][1]);
                *(float2*)(Cf + o0 + 8 * DM) = make_float2(acc[mf][nf][2], acc[mf][nf][3]);
            } else {
                *(uint32_t*)(Ch + o0) = h2pack(acc[mf][nf][0], acc[mf][nf][1]);
                *(uint32_t*)(Ch + o0 + 8 * DM) = h2pack(acc[mf][nf][2], acc[mf][nf][3]);
            }
        }
    }
}

__global__ void __launch_bounds__(128, 2)
hgemm_qkv(const __half* __restrict__ A, const __half* __restrict__ Wall,
          __half* __restrict__ q, __half* __restrict__ k, __half* __restrict__ v)
{
    extern __shared__ char smraw[];
    const int wsel = blockIdx.x >> 3;
    const int n0 = (blockIdx.x & 7) * 128;
    const int m0 = blockIdx.y * 128;
    const __half* W = Wall + (size_t)wsel * DM * DM;
    __half* Ch = (wsel == 0) ? q : (wsel == 1) ? k : v;
    hgemm_body<1>(A, W, nullptr, Ch, m0, n0, smem_u32(smraw));
}

__global__ void __launch_bounds__(128, 2)
hgemm_o(const __half* __restrict__ A, const __half* __restrict__ W,
        float* __restrict__ Cf)
{
    extern __shared__ char smraw[];
    hgemm_body<0>(A, W, Cf, nullptr, blockIdx.y * 128, blockIdx.x * 128,
                  smem_u32(smraw));
}

// =================================================================
// FlashAttention-2 style causal ALiBi attention, fp16 HMMA.
// R9 structure; QK product uses fp16 ACCUMULATORS (rate experiment),
// unpacked to fp32 immediately; softmax + PV unchanged (f32 accum).
// smem: Q 16KB + 2 stages x (K 8KB + V 8KB) = 48KB.
// =================================================================
#define AT_Q 128
#define AT_K 64
#define ATT_SMEM (16384 + 32768)

__device__ __forceinline__ void load_kv(uint32_t base,
        const __half* kh, const __half* vh, int b, int h, int kb, int tid)
{
    size_t grow = (size_t)(b * T_ + kb * AT_K) * DM + h * HD;
#pragma unroll
    for (int t = 0; t < 2; t++) {
        int idx = tid + t * 256;
        int r = idx >> 3;
        int c = idx & 7;
        uint32_t sw = swz(r, c);
        size_t off = grow + (size_t)r * DM;
        cp16(base +        sw, (const char*)(kh + off) + c * 16);
        cp16(base + 8192 + sw, (const char*)(vh + off) + c * 16);
    }
}

__global__ void __launch_bounds__(256)
attn_mma(const __half* __restrict__ qh, const __half* __restrict__ kh,
         const __half* __restrict__ vh, __half* __restrict__ oh)
{
    extern __shared__ char smraw[];
    const uint32_t sb = smem_u32(smraw);
    const int tid = threadIdx.x, w = tid >> 5, lane = tid & 31;
    const int h = blockIdx.y, b = blockIdx.z;
    const int i0 = (gridDim.x - 1 - blockIdx.x) * AT_Q;
    const int lrow = lane & 15, lsel = lane >> 4;
    const int rq = lane >> 2, c2 = (lane & 3) * 2;
    const int irow_base = i0 + w * 16;
    const int irow = irow_base + rq;

    const float slope  = ex2(-0.5f * (float)(h + 1));
    const float slope2 = slope * 1.4426950408889634f;
    const float scale2 = 0.18033688011112042f;

    const uint32_t sQ = sb;
    auto stgK = [&](int s) { return sb + 16384 + s * 16384; };

    {
        const char* gq = (const char*)(qh + (size_t)(b * T_ + i0) * DM + h * HD);
#pragma unroll
        for (int t = 0; t < 4; t++) {
            int idx = tid + t * 256;
            int r = idx >> 3;
            int c = idx & 7;
            cp16(sQ + swz(r, c), gq + (size_t)r * DM * 2 + c * 16);
        }
        load_kv(stgK(0), kh, vh, b, h, 0, tid);
        CP_COMMIT();
    }

    uint32_t qf[4][4];
    float O[8][4];
#pragma unroll
    for (int i = 0; i < 8; i++)
#pragma unroll
        for (int e = 0; e < 4; e++) O[i][e] = 0.f;
    float m0 = -1e30f, m1 = -1e30f, l0 = 0.f, l1 = 0.f;

    const int NB = (i0 + AT_Q) / AT_K;

    for (int kb = 0; kb < NB; kb++) {
        int s = kb & 1;
        if (kb + 1 < NB) {
            load_kv(stgK(s ^ 1), kh, vh, b, h, kb + 1, tid);
            CP_COMMIT();
            asm volatile("cp.async.wait_group 1;");
        } else {
            asm volatile("cp.async.wait_group 0;");
        }
        __syncthreads();

        if (kb == 0) {
#pragma unroll
            for (int ks = 0; ks < 4; ks++) {
                int r = w * 16 + lrow;
                uint32_t off = (uint32_t)(r * 128 + (((2 * ks + lsel) ^ (r & 7)) << 4));
                ldsm4(qf[ks], sQ + off);
            }
        }

        if (kb * AT_K <= irow_base + 15) {
            const uint32_t sK = stgK(s), sV = sK + 8192;

            // ---- S = Q K^T with fp16 accumulators (rate experiment)
            uint32_t S16[8][2];
#pragma unroll
            for (int i = 0; i < 8; i++) { S16[i][0] = 0u; S16[i][1] = 0u; }

#pragma unroll
            for (int ks = 0; ks < 4; ks++) {
#pragma unroll
                for (int np = 0; np < 4; np++) {
                    int r = np * 16 + lrow;
                    uint32_t off = (uint32_t)(r * 128 + (((2 * ks + lsel) ^ (r & 7)) << 4));
                    uint32_t bh[4];
                    ldsm4(bh, sK + off);
                    mma_f16acc(S16[2 * np],     qf[ks], bh[0], bh[2]);
                    mma_f16acc(S16[2 * np + 1], qf[ks], bh[1], bh[3]);
                }
            }

            // unpack fp16 accs -> fp32 S (same layout as before)
            float S[8][4];
#pragma unroll
            for (int nf = 0; nf < 8; nf++) {
                float2 u0 = h2unpack(S16[nf][0]);
                float2 u1 = h2unpack(S16[nf][1]);
                S[nf][0] = u0.x; S[nf][1] = u0.y;
                S[nf][2] = u1.x; S[nf][3] = u1.y;
            }

            const int jb = kb * AT_K + c2;
            const bool nomask = (kb * AT_K + 63) <= irow_base;
            float rm0 = -1e30f, rm1 = -1e30f;
#pragma unroll
            for (int nf = 0; nf < 8; nf++) {
                int d0 = irow - (jb + 8 * nf);
                float fd = (float)d0;
                float bia = -slope2 * fd;
                float t0 = fmaf(S[nf][0], scale2, bia);
                float t1 = fmaf(S[nf][1], scale2, bia + slope2);
                float t2 = fmaf(S[nf][2], scale2, bia - 8.f * slope2);
                float t3 = fmaf(S[nf][3], scale2, bia - 7.f * slope2);
                if (!nomask) {
                    t0 = (d0 >= 0)  ? t0 : -1e30f;
                    t1 = (d0 >= 1)  ? t1 : -1e30f;
                    t2 = (d0 >= -8) ? t2 : -1e30f;
                    t3 = (d0 >= -7) ? t3 : -1e30f;
                }
                S[nf][0] = t0; S[nf][1] = t1; S[nf][2] = t2; S[nf][3] = t3;
                rm0 = fmaxf(rm0, fmaxf(t0, t1));
                rm1 = fmaxf(rm1, fmaxf(t2, t3));
            }
            rm0 = fmaxf(rm0, __shfl_xor_sync(0xffffffffu, rm0, 1));
            rm0 = fmaxf(rm0, __shfl_xor_sync(0xffffffffu, rm0, 2));
            rm1 = fmaxf(rm1, __shfl_xor_sync(0xffffffffu, rm1, 1));
            rm1 = fmaxf(rm1, __shfl_xor_sync(0xffffffffu, rm1, 2));

            float m0n = fmaxf(m0, rm0), m1n = fmaxf(m1, rm1);
            float cr0 = ex2(m0 - m0n), cr1 = ex2(m1 - m1n);
            m0 = m0n; m1 = m1n;
            l0 *= cr0; l1 *= cr1;
#pragma unroll
            for (int nf = 0; nf < 8; nf++) {
                O[nf][0] *= cr0; O[nf][1] *= cr0;
                O[nf][2] *= cr1; O[nf][3] *= cr1;
            }
#pragma unroll
            for (int nf = 0; nf < 8; nf++) {
                float p0 = ex2(S[nf][0] - m0);
                float p1 = ex2(S[nf][1] - m0);
                float p2 = ex2(S[nf][2] - m1);
                float p3 = ex2(S[nf][3] - m1);
                S[nf][0] = p0; S[nf][1] = p1; S[nf][2] = p2; S[nf][3] = p3;
                l0 += p0 + p1;
                l1 += p2 + p3;
            }

#pragma unroll
            for (int ks2 = 0; ks2 < 4; ks2++) {
                uint32_t af2[4];
                af2[0] = h2pack(S[2 * ks2][0],     S[2 * ks2][1]);
                af2[1] = h2pack(S[2 * ks2][2],     S[2 * ks2][3]);
                af2[2] = h2pack(S[2 * ks2 + 1][0], S[2 * ks2 + 1][1]);
                af2[3] = h2pack(S[2 * ks2 + 1][2], S[2 * ks2 + 1][3]);
#pragma unroll
                for (int nf2 = 0; nf2 < 4; nf2++) {
                    int r = ks2 * 16 + lrow;
                    uint32_t off = (uint32_t)(r * 128 + (((2 * nf2 + lsel) ^ (r & 7)) << 4));
                    uint32_t bh[4];
                    ldsm4t(bh, sV + off);
                    mma_f16(O[2 * nf2],     af2, bh[0], bh[1]);
                    mma_f16(O[2 * nf2 + 1], af2, bh[2], bh[3]);
                }
            }
        }
        __syncthreads();
    }

    l0 += __shfl_xor_sync(0xffffffffu, l0, 1);
    l0 += __shfl_xor_sync(0xffffffffu, l0, 2);
    l1 += __shfl_xor_sync(0xffffffffu, l1, 1);
    l1 += __shfl_xor_sync(0xffffffffu, l1, 2);
    float iv0 = 1.0f / l0, iv1 = 1.0f / l1;

    size_t obase = (size_t)(b * T_ + irow) * DM + h * HD + c2;
#pragma unroll
    for (int nf = 0; nf < 8; nf++) {
        *(uint32_t*)(oh + obase + 8 * nf) =
            h2pack(O[nf][0] * iv0, O[nf][1] * iv0);
        *(uint32_t*)(oh + obase + 8 * DM + 8 * nf) =
            h2pack(O[nf][2] * iv1, O[nf][3] * iv1);
    }
}

// =================================================================
extern "C" void kernel_launch(void* const* d_in, const int* in_sizes, int n_in,
                              void* d_out, int out_size)
{
    const float* x  = (const float*)d_in[0];
    const float* Wq = (const float*)d_in[1];
    const float* Wk = (const float*)d_in[2];
    const float* Wv = (const float*)d_in[3];
    const float* Wo = (const float*)d_in[4];
    float* out = (float*)d_out;

    __half *xh, *wh, *qh, *kh, *vh, *ah;
    cudaGetSymbolAddress((void**)&xh, g_xh);
    cudaGetSymbolAddress((void**)&wh, g_wh);
    cudaGetSymbolAddress((void**)&qh, g_qh);
    cudaGetSymbolAddress((void**)&kh, g_kh);
    cudaGetSymbolAddress((void**)&vh, g_vh);
    cudaGetSymbolAddress((void**)&ah, g_ah);

    cudaFuncSetAttribute(hgemm_qkv,
                         cudaFuncAttributeMaxDynamicSharedMemorySize, GEMM_SMEM);
    cudaFuncSetAttribute(hgemm_o,
                         cudaFuncAttributeMaxDynamicSharedMemorySize, GEMM_SMEM);
    cudaFuncSetAttribute(attn_mma,
                         cudaFuncAttributeMaxDynamicSharedMemorySize, ATT_SMEM);

    conv_all<<<(NX4 + 4 * NW4) / 256, 256>>>(x, Wq, Wk, Wv, Wo, xh, wh);

    hgemm_qkv<<<dim3(24, ROWS / 128), 128, GEMM_SMEM>>>(xh, wh, qh, kh, vh);

    dim3 agrid(T_ / AT_Q, H_, B_);      // (16, 16, 2)
    attn_mma<<<agrid, 256, ATT_SMEM>>>(qh, kh, vh, ah);

    hgemm_o<<<dim3(DM / 128, ROWS / 128), 128, GEMM_SMEM>>>(
        ah, wh + 3 * (size_t)DM * DM, out);
}

// round 14
// speedup vs baseline: 1.0379x; 1.0004x over previous
#include <cuda_runtime.h>
#include <cuda_fp16.h>
#include <cstdint>

#define B_   2
#define T_   2048
#define DM   1024
#define H_   16
#define HD   64
#define ROWS (B_ * T_)        // 4096

// ---------------- scratch (no cudaMalloc allowed) ----------------
__device__ __half g_xh[ROWS * DM];
__device__ __half g_wh[4 * DM * DM];   // Wq, Wk, Wv, Wo (fp16)
__device__ __half g_qh[ROWS * DM];
__device__ __half g_kh[ROWS * DM];
__device__ __half g_vh[ROWS * DM];
__device__ __half g_ah[ROWS * DM];

// =================================================================
// low-level helpers
// =================================================================
__device__ __forceinline__ uint32_t smem_u32(const void* p) {
    uint32_t a;
    asm("{ .reg .u64 t; cvta.to.shared.u64 t, %1; cvt.u32.u64 %0, t; }"
        : "=r"(a) : "l"(p));
    return a;
}
__device__ __forceinline__ void cp16(uint32_t dst, const void* src) {
    asm volatile("cp.async.cg.shared.global [%0], [%1], 16;" :: "r"(dst), "l"(src));
}
#define CP_COMMIT() asm volatile("cp.async.commit_group;")

// PDL hooks (sm_90 baseline PTX; no-ops when launched without PDL attrs)
#define GRID_TRIGGER() asm volatile("griddepcontrol.launch_dependents;" ::: "memory")
#define GRID_WAIT()    asm volatile("griddepcontrol.wait;" ::: "memory")

__device__ __forceinline__ void ldsm4(uint32_t (&r)[4], uint32_t addr) {
    asm volatile("ldmatrix.sync.aligned.m8n8.x4.shared.b16 {%0,%1,%2,%3}, [%4];"
                 : "=r"(r[0]), "=r"(r[1]), "=r"(r[2]), "=r"(r[3]) : "r"(addr));
}
__device__ __forceinline__ void ldsm4t(uint32_t (&r)[4], uint32_t addr) {
    asm volatile("ldmatrix.sync.aligned.m8n8.x4.trans.shared.b16 {%0,%1,%2,%3}, [%4];"
                 : "=r"(r[0]), "=r"(r[1]), "=r"(r[2]), "=r"(r[3]) : "r"(addr));
}
__device__ __forceinline__ void mma_f16(float (&d)[4], const uint32_t (&a)[4],
                                        uint32_t b0, uint32_t b1) {
    asm volatile(
        "mma.sync.aligned.m16n8k16.row.col.f32.f16.f16.f32 "
        "{%0,%1,%2,%3}, {%4,%5,%6,%7}, {%8,%9}, {%0,%1,%2,%3};"
        : "+f"(d[0]), "+f"(d[1]), "+f"(d[2]), "+f"(d[3])
        : "r"(a[0]), "r"(a[1]), "r"(a[2]), "r"(a[3]), "r"(b0), "r"(b1));
}
__device__ __forceinline__ float ex2(float x) {
    float y;
    asm("ex2.approx.ftz.f32 %0, %1;" : "=f"(y) : "f"(x));
    return y;
}
__device__ __forceinline__ uint32_t h2pack(float c0, float c1) {
    uint32_t r;
    asm("cvt.rn.f16x2.f32 %0, %1, %2;" : "=r"(r) : "f"(c1), "f"(c0));
    return r;
}
__device__ __forceinline__ uint32_t swz(int r, int c) {
    return (uint32_t)(r * 128 + ((c ^ (r & 7)) << 4));
}

// =================================================================
// single fused fp32 -> fp16 convert: x (1M float4) + 4 W (256K each)
// =================================================================
#define NX4 (ROWS * DM / 4)   // 1048576
#define NW4 (DM * DM / 4)     // 262144

__global__ void __launch_bounds__(256)
conv_all(const float* __restrict__ x,
         const float* __restrict__ w0, const float* __restrict__ w1,
         const float* __restrict__ w2, const float* __restrict__ w3,
         __half* __restrict__ xh, __half* __restrict__ wh)
{
    GRID_TRIGGER();     // let hgemm_qkv begin launching early
    int i = blockIdx.x * blockDim.x + threadIdx.x;
    const float* src;
    __half* dst;
    int off;
    if (i < NX4) {
        src = x; dst = xh; off = i;
    } else {
        int j = i - NX4;
        int w = j >> 18;
        off = j & (NW4 - 1);
        src = (w == 0) ? w0 : (w == 1) ? w1 : (w == 2) ? w2 : w3;
        dst = wh + (size_t)w * DM * DM;
    }
    float4 v = ((const float4*)src)[off];
    uint2 o;
    o.x = h2pack(v.x, v.y);
    o.y = h2pack(v.z, v.w);
    ((uint2*)dst)[off] = o;
}

// =================================================================
// fp16 HMMA GEMM (R9 body): CTA 128x128, 4 warps m64n64, BK=64,
// 3-stage single-sync pipeline + register frag double buffer.
// PDL=1 variant prefetches W chunks BEFORE griddepcontrol.wait.
// =================================================================
#define GBK      64
#define NKC      (DM / GBK)     // 16
#define TILE_B   (128 * 128)    // 16 KB per 128x64-fp16 tile
#define STAGE_B  (2 * TILE_B)   // A tile + W tile
#define GEMM_SMEM (3 * STAGE_B) // 96 KB

__device__ __forceinline__ void load_tile128(uint32_t dst, const __half* g,
                                             int row0, int k0, int tid) {
    const char* gb = (const char*)(g + (size_t)row0 * DM + k0);
#pragma unroll
    for (int it = 0; it < 8; it++) {
        int idx = tid + it * 128;
        int r = idx >> 3;
        int c = idx & 7;
        cp16(dst + swz(r, c), gb + (size_t)r * DM * 2 + c * 16);
    }
}

template<int MODE, int PDLW>
__device__ __forceinline__ void hgemm_body(
    const __half* __restrict__ A, const __half* __restrict__ W,
    float* __restrict__ Cf, __half* __restrict__ Ch,
    int m0, int n0, uint32_t sb)
{
    const int tid = threadIdx.x;
    const int wid = tid >> 5;
    const int lane = tid & 31;
    const int wm = wid >> 1;
    const int wn = wid & 1;
    const int lrow = lane & 15;
    const int lsel = lane >> 4;

    int arow[4], brow[4];
#pragma unroll
    for (int mf = 0; mf < 4; mf++) arow[mf] = wm * 64 + mf * 16 + lrow;
#pragma unroll
    for (int nf = 0; nf < 4; nf++) brow[nf] = wn * 64 + nf * 16 + lrow;

    float acc[4][8][4];
#pragma unroll
    for (int i = 0; i < 4; i++)
#pragma unroll
        for (int j = 0; j < 8; j++)
#pragma unroll
            for (int e = 0; e < 4; e++) acc[i][j][e] = 0.f;

    auto stage = [&](int s) { return sb + s * STAGE_B; };

    if (PDLW) {
        // W (independent of upstream grid) first, then wait, then A.
        // Groups: G1={W0,W1}  G2={A0}  G3={A1}.  FIFO retirement keeps
        // the steady-state wait_group 1 discipline of the main loop valid.
        load_tile128(stage(0) + 1 * TILE_B, W, n0, 0, tid);
        load_tile128(stage(1) + 1 * TILE_B, W, n0, GBK, tid);
        CP_COMMIT();
        GRID_WAIT();
        load_tile128(stage(0) + 0 * TILE_B, A, m0, 0, tid);
        CP_COMMIT();
        load_tile128(stage(1) + 0 * TILE_B, A, m0, GBK, tid);
        CP_COMMIT();
    } else {
        load_tile128(stage(0) + 0 * TILE_B, A, m0, 0, tid);
        load_tile128(stage(0) + 1 * TILE_B, W, n0, 0, tid);
        CP_COMMIT();
        load_tile128(stage(1) + 0 * TILE_B, A, m0, GBK, tid);
        load_tile128(stage(1) + 1 * TILE_B, W, n0, GBK, tid);
        CP_COMMIT();
    }

    uint32_t af[2][4][4], bf[2][4][4];

    for (int kc = 0; kc < NKC; kc++) {
        if (kc + 1 < NKC) {
            asm volatile("cp.async.wait_group 1;");
        } else {
            asm volatile("cp.async.wait_group 0;");
        }
        __syncthreads();

        if (kc + 2 < NKC) {
            int s2 = (kc + 2) % 3;
            int k0 = (kc + 2) * GBK;
            load_tile128(stage(s2) + 0 * TILE_B, A, m0, k0, tid);
            load_tile128(stage(s2) + 1 * TILE_B, W, n0, k0, tid);
            CP_COMMIT();
        }

        const uint32_t sA = stage(kc % 3) + 0 * TILE_B;
        const uint32_t sW = stage(kc % 3) + 1 * TILE_B;

        auto ldfrags = [&](int buf, int t) {
            const int c0 = t * 2;
#pragma unroll
            for (int mf = 0; mf < 4; mf++) {
                int r = arow[mf];
                ldsm4(af[buf][mf], sA + (uint32_t)(r * 128 + (((c0 + lsel) ^ (r & 7)) << 4)));
            }
#pragma unroll
            for (int nf = 0; nf < 4; nf++) {
                int r = brow[nf];
                ldsm4(bf[buf][nf], sW + (uint32_t)(r * 128 + (((c0 + lsel) ^ (r & 7)) << 4)));
            }
        };

        ldfrags(0, 0);
#pragma unroll
        for (int t = 0; t < 4; t++) {
            if (t < 3) ldfrags((t + 1) & 1, t + 1);
            const int cb = t & 1;
#pragma unroll
            for (int mf = 0; mf < 4; mf++) {
#pragma unroll
                for (int nf = 0; nf < 4; nf++) {
                    mma_f16(acc[mf][2 * nf],     af[cb][mf], bf[cb][nf][0], bf[cb][nf][2]);
                    mma_f16(acc[mf][2 * nf + 1], af[cb][mf], bf[cb][nf][1], bf[cb][nf][3]);
                }
            }
        }
    }

    const int erow = m0 + wm * 64 + (lane >> 2);
    const int ecol = n0 + wn * 64 + (lane & 3) * 2;
#pragma unroll
    for (int mf = 0; mf < 4; mf++) {
#pragma unroll
        for (int nf = 0; nf < 8; nf++) {
            size_t o0 = (size_t)(erow + mf * 16) * DM + ecol + nf * 8;
            if (MODE == 0) {
                *(float2*)(Cf + o0) = make_float2(acc[mf][nf][0], acc[mf][nf][1]);
                *(float2*)(Cf + o0 + 8 * DM) = make_float2(acc[mf][nf][2], acc[mf][nf][3]);
            } else {
                *(uint32_t*)(Ch + o0) = h2pack(acc[mf][nf][0], acc[mf][nf][1]);
                *(uint32_t*)(Ch + o0 + 8 * DM) = h2pack(acc[mf][nf][2], acc[mf][nf][3]);
            }
        }
    }
}

__global__ void __launch_bounds__(128, 2)
hgemm_qkv(const __half* __restrict__ A, const __half* __restrict__ Wall,
          __half* __restrict__ q, __half* __restrict__ k, __half* __restrict__ v)
{
    extern __shared__ char smraw[];
    GRID_TRIGGER();   // let attn begin launching early
    GRID_WAIT();      // wait for conv_all (x and W are both dependent)
    const int wsel = blockIdx.x >> 3;
    const int n0 = (blockIdx.x & 7) * 128;
    const int m0 = blockIdx.y * 128;
    const __half* W = Wall + (size_t)wsel * DM * DM;
    __half* Ch = (wsel == 0) ? q : (wsel == 1) ? k : v;
    hgemm_body<1, 0>(A, W, nullptr, Ch, m0, n0, smem_u32(smraw));
}

__global__ void __launch_bounds__(128, 2)
hgemm_o(const __half* __restrict__ A, const __half* __restrict__ W,
        float* __restrict__ Cf)
{
    extern __shared__ char smraw[];
    // PDLW=1: prefetch Wo chunks (independent of attention), then wait.
    hgemm_body<0, 1>(A, W, Cf, nullptr, blockIdx.y * 128, blockIdx.x * 128,
                     smem_u32(smraw));
}

// =================================================================
// FlashAttention-2 style causal ALiBi attention (R9 exact body +
// PDL trigger/wait). smem: Q 16KB + 2 stages x (K 8KB + V 8KB) = 48KB.
// =================================================================
#define AT_Q 128
#define AT_K 64
#define ATT_SMEM (16384 + 32768)

__device__ __forceinline__ void load_kv(uint32_t base,
        const __half* kh, const __half* vh, int b, int h, int kb, int tid)
{
    size_t grow = (size_t)(b * T_ + kb * AT_K) * DM + h * HD;
#pragma unroll
    for (int t = 0; t < 2; t++) {
        int idx = tid + t * 256;
        int r = idx >> 3;
        int c = idx & 7;
        uint32_t sw = swz(r, c);
        size_t off = grow + (size_t)r * DM;
        cp16(base +        sw, (const char*)(kh + off) + c * 16);
        cp16(base + 8192 + sw, (const char*)(vh + off) + c * 16);
    }
}

__global__ void __launch_bounds__(256)
attn_mma(const __half* __restrict__ qh, const __half* __restrict__ kh,
         const __half* __restrict__ vh, __half* __restrict__ oh)
{
    extern __shared__ char smraw[];
    GRID_TRIGGER();   // let hgemm_o begin launching (it prefetches Wo, then waits)
    GRID_WAIT();      // wait for hgemm_qkv (q/k/v all dependent)
    const uint32_t sb = smem_u32(smraw);
    const int tid = threadIdx.x, w = tid >> 5, lane = tid & 31;
    const int h = blockIdx.y, b = blockIdx.z;
    const int i0 = (gridDim.x - 1 - blockIdx.x) * AT_Q;
    const int lrow = lane & 15, lsel = lane >> 4;
    const int rq = lane >> 2, c2 = (lane & 3) * 2;
    const int irow_base = i0 + w * 16;
    const int irow = irow_base + rq;

    const float slope  = ex2(-0.5f * (float)(h + 1));
    const float slope2 = slope * 1.4426950408889634f;
    const float scale2 = 0.18033688011112042f;

    const uint32_t sQ = sb;
    auto stgK = [&](int s) { return sb + 16384 + s * 16384; };

    {
        const char* gq = (const char*)(qh + (size_t)(b * T_ + i0) * DM + h * HD);
#pragma unroll
        for (int t = 0; t < 4; t++) {
            int idx = tid + t * 256;
            int r = idx >> 3;
            int c = idx & 7;
            cp16(sQ + swz(r, c), gq + (size_t)r * DM * 2 + c * 16);
        }
        load_kv(stgK(0), kh, vh, b, h, 0, tid);
        CP_COMMIT();
    }

    uint32_t qf[4][4];
    float O[8][4];
#pragma unroll
    for (int i = 0; i < 8; i++)
#pragma unroll
        for (int e = 0; e < 4; e++) O[i][e] = 0.f;
    float m0 = -1e30f, m1 = -1e30f, l0 = 0.f, l1 = 0.f;

    const int NB = (i0 + AT_Q) / AT_K;

    for (int kb = 0; kb < NB; kb++) {
        int s = kb & 1;
        if (kb + 1 < NB) {
            load_kv(stgK(s ^ 1), kh, vh, b, h, kb + 1, tid);
            CP_COMMIT();
            asm volatile("cp.async.wait_group 1;");
        } else {
            asm volatile("cp.async.wait_group 0;");
        }
        __syncthreads();

        if (kb == 0) {
#pragma unroll
            for (int ks = 0; ks < 4; ks++) {
                int r = w * 16 + lrow;
                uint32_t off = (uint32_t)(r * 128 + (((2 * ks + lsel) ^ (r & 7)) << 4));
                ldsm4(qf[ks], sQ + off);
            }
        }

        if (kb * AT_K <= irow_base + 15) {
            const uint32_t sK = stgK(s), sV = sK + 8192;

            float S[8][4];
#pragma unroll
            for (int i = 0; i < 8; i++)
#pragma unroll
                for (int e = 0; e < 4; e++) S[i][e] = 0.f;

#pragma unroll
            for (int ks = 0; ks < 4; ks++) {
#pragma unroll
                for (int np = 0; np < 4; np++) {
                    int r = np * 16 + lrow;
                    uint32_t off = (uint32_t)(r * 128 + (((2 * ks + lsel) ^ (r & 7)) << 4));
                    uint32_t bh[4];
                    ldsm4(bh, sK + off);
                    mma_f16(S[2 * np],     qf[ks], bh[0], bh[2]);
                    mma_f16(S[2 * np + 1], qf[ks], bh[1], bh[3]);
                }
            }

            const int jb = kb * AT_K + c2;
            const bool nomask = (kb * AT_K + 63) <= irow_base;
            float rm0 = -1e30f, rm1 = -1e30f;
#pragma unroll
            for (int nf = 0; nf < 8; nf++) {
                int d0 = irow - (jb + 8 * nf);
                float fd = (float)d0;
                float bia = -slope2 * fd;
                float t0 = fmaf(S[nf][0], scale2, bia);
                float t1 = fmaf(S[nf][1], scale2, bia + slope2);
                float t2 = fmaf(S[nf][2], scale2, bia - 8.f * slope2);
                float t3 = fmaf(S[nf][3], scale2, bia - 7.f * slope2);
                if (!nomask) {
                    t0 = (d0 >= 0)  ? t0 : -1e30f;
                    t1 = (d0 >= 1)  ? t1 : -1e30f;
                    t2 = (d0 >= -8) ? t2 : -1e30f;
                    t3 = (d0 >= -7) ? t3 : -1e30f;
                }
                S[nf][0] = t0; S[nf][1] = t1; S[nf][2] = t2; S[nf][3] = t3;
                rm0 = fmaxf(rm0, fmaxf(t0, t1));
                rm1 = fmaxf(rm1, fmaxf(t2, t3));
            }
            rm0 = fmaxf(rm0, __shfl_xor_sync(0xffffffffu, rm0, 1));
            rm0 = fmaxf(rm0, __shfl_xor_sync(0xffffffffu, rm0, 2));
            rm1 = fmaxf(rm1, __shfl_xor_sync(0xffffffffu, rm1, 1));
            rm1 = fmaxf(rm1, __shfl_xor_sync(0xffffffffu, rm1, 2));

            float m0n = fmaxf(m0, rm0), m1n = fmaxf(m1, rm1);
            float cr0 = ex2(m0 - m0n), cr1 = ex2(m1 - m1n);
            m0 = m0n; m1 = m1n;
            l0 *= cr0; l1 *= cr1;
#pragma unroll
            for (int nf = 0; nf < 8; nf++) {
                O[nf][0] *= cr0; O[nf][1] *= cr0;
                O[nf][2] *= cr1; O[nf][3] *= cr1;
            }
#pragma unroll
            for (int nf = 0; nf < 8; nf++) {
                float p0 = ex2(S[nf][0] - m0);
                float p1 = ex2(S[nf][1] - m0);
                float p2 = ex2(S[nf][2] - m1);
                float p3 = ex2(S[nf][3] - m1);
                S[nf][0] = p0; S[nf][1] = p1; S[nf][2] = p2; S[nf][3] = p3;
                l0 += p0 + p1;
                l1 += p2 + p3;
            }

#pragma unroll
            for (int ks2 = 0; ks2 < 4; ks2++) {
                uint32_t af2[4];
                af2[0] = h2pack(S[2 * ks2][0],     S[2 * ks2][1]);
                af2[1] = h2pack(S[2 * ks2][2],     S[2 * ks2][3]);
                af2[2] = h2pack(S[2 * ks2 + 1][0], S[2 * ks2 + 1][1]);
                af2[3] = h2pack(S[2 * ks2 + 1][2], S[2 * ks2 + 1][3]);
#pragma unroll
                for (int nf2 = 0; nf2 < 4; nf2++) {
                    int r = ks2 * 16 + lrow;
                    uint32_t off = (uint32_t)(r * 128 + (((2 * nf2 + lsel) ^ (r & 7)) << 4));
                    uint32_t bh[4];
                    ldsm4t(bh, sV + off);
                    mma_f16(O[2 * nf2],     af2, bh[0], bh[1]);
                    mma_f16(O[2 * nf2 + 1], af2, bh[2], bh[3]);
                }
            }
        }
        __syncthreads();
    }

    l0 += __shfl_xor_sync(0xffffffffu, l0, 1);
    l0 += __shfl_xor_sync(0xffffffffu, l0, 2);
    l1 += __shfl_xor_sync(0xffffffffu, l1, 1);
    l1 += __shfl_xor_sync(0xffffffffu, l1, 2);
    float iv0 = 1.0f / l0, iv1 = 1.0f / l1;

    size_t obase = (size_t)(b * T_ + irow) * DM + h * HD + c2;
#pragma unroll
    for (int nf = 0; nf < 8; nf++) {
        *(uint32_t*)(oh + obase + 8 * nf) =
            h2pack(O[nf][0] * iv0, O[nf][1] * iv0);
        *(uint32_t*)(oh + obase + 8 * DM + 8 * nf) =
            h2pack(O[nf][2] * iv1, O[nf][3] * iv1);
    }
}

// =================================================================
extern "C" void kernel_launch(void* const* d_in, const int* in_sizes, int n_in,
                              void* d_out, int out_size)
{
    const float* x  = (const float*)d_in[0];
    const float* Wq = (const float*)d_in[1];
    const float* Wk = (const float*)d_in[2];
    const float* Wv = (const float*)d_in[3];
    const float* Wo = (const float*)d_in[4];
    float* out = (float*)d_out;

    __half *xh, *wh, *qh, *kh, *vh, *ah;
    cudaGetSymbolAddress((void**)&xh, g_xh);
    cudaGetSymbolAddress((void**)&wh, g_wh);
    cudaGetSymbolAddress((void**)&qh, g_qh);
    cudaGetSymbolAddress((void**)&kh, g_kh);
    cudaGetSymbolAddress((void**)&vh, g_vh);
    cudaGetSymbolAddress((void**)&ah, g_ah);

    cudaFuncSetAttribute(hgemm_qkv,
                         cudaFuncAttributeMaxDynamicSharedMemorySize, GEMM_SMEM);
    cudaFuncSetAttribute(hgemm_o,
                         cudaFuncAttributeMaxDynamicSharedMemorySize, GEMM_SMEM);
    cudaFuncSetAttribute(attn_mma,
                         cudaFuncAttributeMaxDynamicSharedMemorySize, ATT_SMEM);

    // PDL attribute shared by the three dependent launches
    cudaLaunchAttribute pdl[1];
    pdl[0].id = cudaLaunchAttributeProgrammaticStreamSerialization;
    pdl[0].val.programmaticStreamSerializationAllowed = 1;

    // 1) fused converts (normal launch; triggers dependents early)
    conv_all<<<(NX4 + 4 * NW4) / 256, 256>>>(x, Wq, Wk, Wv, Wo, xh, wh);

    // 2) fused QKV projections (PDL consumer of conv, producer for attn)
    {
        cudaLaunchConfig_t cfg = {};
        cfg.gridDim = dim3(24, ROWS / 128);
        cfg.blockDim = dim3(128);
        cfg.dynamicSmemBytes = GEMM_SMEM;
        cfg.stream = 0;
        cfg.attrs = pdl;
        cfg.numAttrs = 1;
        cudaLaunchKernelEx(&cfg, hgemm_qkv,
                           (const __half*)xh, (const __half*)wh, qh, kh, vh);
    }

    // 3) attention (PDL consumer of qkv, producer for hgemm_o)
    {
        cudaLaunchConfig_t cfg = {};
        cfg.gridDim = dim3(T_ / AT_Q, H_, B_);   // (16, 16, 2)
        cfg.blockDim = dim3(256);
        cfg.dynamicSmemBytes = ATT_SMEM;
        cfg.stream = 0;
        cfg.attrs = pdl;
        cfg.numAttrs = 1;
        cudaLaunchKernelEx(&cfg, attn_mma,
                           (const __half*)qh, (const __half*)kh,
                           (const __half*)vh, ah);
    }

    // 4) output projection (PDL consumer; prefetches Wo before wait)
    {
        cudaLaunchConfig_t cfg = {};
        cfg.gridDim = dim3(DM / 128, ROWS / 128);
        cfg.blockDim = dim3(128);
        cfg.dynamicSmemBytes = GEMM_SMEM;
        cfg.stream = 0;
        cfg.attrs = pdl;
        cfg.numAttrs = 1;
        cudaLaunchKernelEx(&cfg, hgemm_o,
                           (const __half*)ah,
                           (const __half*)(wh + 3 * (size_t)DM * DM), out);
    }
}

// round 15
// speedup vs baseline: 1.0556x; 1.0171x over previous
#include <cuda_runtime.h>
#include <cuda_fp16.h>
#include <cstdint>

#define B_   2
#define T_   2048
#define DM   1024
#define H_   16
#define HD   64
#define ROWS (B_ * T_)        // 4096

// ---------------- scratch (no cudaMalloc allowed) ----------------
__device__ __half g_xh[ROWS * DM];
__device__ __half g_wh[4 * DM * DM];   // Wq, Wk, Wv, Wo (fp16)
__device__ __half g_qh[ROWS * DM];
__device__ __half g_kh[ROWS * DM];
__device__ __half g_vh[ROWS * DM];
__device__ __half g_ah[ROWS * DM];

// =================================================================
// low-level helpers
// =================================================================
__device__ __forceinline__ uint32_t smem_u32(const void* p) {
    uint32_t a;
    asm("{ .reg .u64 t; cvta.to.shared.u64 t, %1; cvt.u32.u64 %0, t; }"
        : "=r"(a) : "l"(p));
    return a;
}
__device__ __forceinline__ void cp16(uint32_t dst, const void* src) {
    asm volatile("cp.async.cg.shared.global [%0], [%1], 16;" :: "r"(dst), "l"(src));
}
#define CP_COMMIT() asm volatile("cp.async.commit_group;")

// PDL hooks (sm_90 baseline PTX)
#define GRID_TRIGGER() asm volatile("griddepcontrol.launch_dependents;" ::: "memory")
#define GRID_WAIT()    asm volatile("griddepcontrol.wait;" ::: "memory")

__device__ __forceinline__ void ldsm4(uint32_t (&r)[4], uint32_t addr) {
    asm volatile("ldmatrix.sync.aligned.m8n8.x4.shared.b16 {%0,%1,%2,%3}, [%4];"
                 : "=r"(r[0]), "=r"(r[1]), "=r"(r[2]), "=r"(r[3]) : "r"(addr));
}
__device__ __forceinline__ void ldsm4t(uint32_t (&r)[4], uint32_t addr) {
    asm volatile("ldmatrix.sync.aligned.m8n8.x4.trans.shared.b16 {%0,%1,%2,%3}, [%4];"
                 : "=r"(r[0]), "=r"(r[1]), "=r"(r[2]), "=r"(r[3]) : "r"(addr));
}
__device__ __forceinline__ void mma_f16(float (&d)[4], const uint32_t (&a)[4],
                                        uint32_t b0, uint32_t b1) {
    asm volatile(
        "mma.sync.aligned.m16n8k16.row.col.f32.f16.f16.f32 "
        "{%0,%1,%2,%3}, {%4,%5,%6,%7}, {%8,%9}, {%0,%1,%2,%3};"
        : "+f"(d[0]), "+f"(d[1]), "+f"(d[2]), "+f"(d[3])
        : "r"(a[0]), "r"(a[1]), "r"(a[2]), "r"(a[3]), "r"(b0), "r"(b1));
}
__device__ __forceinline__ float ex2(float x) {
    float y;
    asm("ex2.approx.ftz.f32 %0, %1;" : "=f"(y) : "f"(x));
    return y;
}
__device__ __forceinline__ uint32_t h2pack(float c0, float c1) {
    uint32_t r;
    asm("cvt.rn.f16x2.f32 %0, %1, %2;" : "=r"(r) : "f"(c1), "f"(c0));
    return r;
}
__device__ __forceinline__ uint32_t swz(int r, int c) {
    return (uint32_t)(r * 128 + ((c ^ (r & 7)) << 4));
}

// =================================================================
// fused fp32 -> fp16 convert with MLP=4: x (1M float4) + 4 W
// (256K float4 each). 2M items total; 4 items per thread.
// Chunk boundaries are 1024-item aligned -> block-uniform tensor.
// =================================================================
#define NX4 (ROWS * DM / 4)   // 1048576
#define NW4 (DM * DM / 4)     // 262144
#define CONV_TOTAL (NX4 + 4 * NW4)   // 2097152
#define CONV_BLOCKS (CONV_TOTAL / 1024)

__global__ void __launch_bounds__(256)
conv_all(const float* __restrict__ x,
         const float* __restrict__ w0, const float* __restrict__ w1,
         const float* __restrict__ w2, const float* __restrict__ w3,
         __half* __restrict__ xh, __half* __restrict__ wh)
{
    GRID_TRIGGER();
    const int base = blockIdx.x * 1024 + threadIdx.x;

    // 4 independent loads first (MLP=4), then convert+store
    float4 v[4];
    const float4* srcp[4];
    uint2* dstp[4];
#pragma unroll
    for (int j = 0; j < 4; j++) {
        int i = base + j * 256;
        const float* src;
        __half* dst;
        int off;
        if (i < NX4) {
            src = x; dst = xh; off = i;
        } else {
            int jj = i - NX4;
            int w = jj >> 18;
            off = jj & (NW4 - 1);
            src = (w == 0) ? w0 : (w == 1) ? w1 : (w == 2) ? w2 : w3;
            dst = wh + (size_t)w * DM * DM;
        }
        srcp[j] = (const float4*)src + off;
        dstp[j] = (uint2*)dst + off;
    }
#pragma unroll
    for (int j = 0; j < 4; j++) v[j] = *srcp[j];
#pragma unroll
    for (int j = 0; j < 4; j++) {
        uint2 o;
        o.x = h2pack(v[j].x, v[j].y);
        o.y = h2pack(v[j].z, v[j].w);
        *dstp[j] = o;
    }
}

// =================================================================
// fp16 HMMA GEMM (R9 body): CTA 128x128, 4 warps m64n64, BK=64,
// 3-stage single-sync pipeline + register frag double buffer.
// PDLW=1 prefetches W chunks BEFORE griddepcontrol.wait.
// =================================================================
#define GBK      64
#define NKC      (DM / GBK)     // 16
#define TILE_B   (128 * 128)    // 16 KB per 128x64-fp16 tile
#define STAGE_B  (2 * TILE_B)   // A tile + W tile
#define GEMM_SMEM (3 * STAGE_B) // 96 KB

__device__ __forceinline__ void load_tile128(uint32_t dst, const __half* g,
                                             int row0, int k0, int tid) {
    const char* gb = (const char*)(g + (size_t)row0 * DM + k0);
#pragma unroll
    for (int it = 0; it < 8; it++) {
        int idx = tid + it * 128;
        int r = idx >> 3;
        int c = idx & 7;
        cp16(dst + swz(r, c), gb + (size_t)r * DM * 2 + c * 16);
    }
}

template<int MODE, int PDLW>
__device__ __forceinline__ void hgemm_body(
    const __half* __restrict__ A, const __half* __restrict__ W,
    float* __restrict__ Cf, __half* __restrict__ Ch,
    int m0, int n0, uint32_t sb)
{
    const int tid = threadIdx.x;
    const int wid = tid >> 5;
    const int lane = tid & 31;
    const int wm = wid >> 1;
    const int wn = wid & 1;
    const int lrow = lane & 15;
    const int lsel = lane >> 4;

    int arow[4], brow[4];
#pragma unroll
    for (int mf = 0; mf < 4; mf++) arow[mf] = wm * 64 + mf * 16 + lrow;
#pragma unroll
    for (int nf = 0; nf < 4; nf++) brow[nf] = wn * 64 + nf * 16 + lrow;

    float acc[4][8][4];
#pragma unroll
    for (int i = 0; i < 4; i++)
#pragma unroll
        for (int j = 0; j < 8; j++)
#pragma unroll
            for (int e = 0; e < 4; e++) acc[i][j][e] = 0.f;

    auto stage = [&](int s) { return sb + s * STAGE_B; };

    if (PDLW) {
        // W first (independent of upstream grid), then wait, then A.
        // Groups: G1={W0,W1}  G2={A0}  G3={A1}; FIFO retirement keeps the
        // steady-state wait_group 1 discipline of the main loop valid.
        load_tile128(stage(0) + 1 * TILE_B, W, n0, 0, tid);
        load_tile128(stage(1) + 1 * TILE_B, W, n0, GBK, tid);
        CP_COMMIT();
        GRID_WAIT();
        load_tile128(stage(0) + 0 * TILE_B, A, m0, 0, tid);
        CP_COMMIT();
        load_tile128(stage(1) + 0 * TILE_B, A, m0, GBK, tid);
        CP_COMMIT();
    } else {
        load_tile128(stage(0) + 0 * TILE_B, A, m0, 0, tid);
        load_tile128(stage(0) + 1 * TILE_B, W, n0, 0, tid);
        CP_COMMIT();
        load_tile128(stage(1) + 0 * TILE_B, A, m0, GBK, tid);
        load_tile128(stage(1) + 1 * TILE_B, W, n0, GBK, tid);
        CP_COMMIT();
    }

    uint32_t af[2][4][4], bf[2][4][4];

    for (int kc = 0; kc < NKC; kc++) {
        if (kc + 1 < NKC) {
            asm volatile("cp.async.wait_group 1;");
        } else {
            asm volatile("cp.async.wait_group 0;");
        }
        __syncthreads();

        if (kc + 2 < NKC) {
            int s2 = (kc + 2) % 3;
            int k0 = (kc + 2) * GBK;
            load_tile128(stage(s2) + 0 * TILE_B, A, m0, k0, tid);
            load_tile128(stage(s2) + 1 * TILE_B, W, n0, k0, tid);
            CP_COMMIT();
        }

        const uint32_t sA = stage(kc % 3) + 0 * TILE_B;
        const uint32_t sW = stage(kc % 3) + 1 * TILE_B;

        auto ldfrags = [&](int buf, int t) {
            const int c0 = t * 2;
#pragma unroll
            for (int mf = 0; mf < 4; mf++) {
                int r = arow[mf];
                ldsm4(af[buf][mf], sA + (uint32_t)(r * 128 + (((c0 + lsel) ^ (r & 7)) << 4)));
            }
#pragma unroll
            for (int nf = 0; nf < 4; nf++) {
                int r = brow[nf];
                ldsm4(bf[buf][nf], sW + (uint32_t)(r * 128 + (((c0 + lsel) ^ (r & 7)) << 4)));
            }
        };

        ldfrags(0, 0);
#pragma unroll
        for (int t = 0; t < 4; t++) {
            if (t < 3) ldfrags((t + 1) & 1, t + 1);
            const int cb = t & 1;
#pragma unroll
            for (int mf = 0; mf < 4; mf++) {
#pragma unroll
                for (int nf = 0; nf < 4; nf++) {
                    mma_f16(acc[mf][2 * nf],     af[cb][mf], bf[cb][nf][0], bf[cb][nf][2]);
                    mma_f16(acc[mf][2 * nf + 1], af[cb][mf], bf[cb][nf][1], bf[cb][nf][3]);
                }
            }
        }
    }

    const int erow = m0 + wm * 64 + (lane >> 2);
    const int ecol = n0 + wn * 64 + (lane & 3) * 2;
#pragma unroll
    for (int mf = 0; mf < 4; mf++) {
#pragma unroll
        for (int nf = 0; nf < 8; nf++) {
            size_t o0 = (size_t)(erow + mf * 16) * DM + ecol + nf * 8;
            if (MODE == 0) {
                *(float2*)(Cf + o0) = make_float2(acc[mf][nf][0], acc[mf][nf][1]);
                *(float2*)(Cf + o0 + 8 * DM) = make_float2(acc[mf][nf][2], acc[mf][nf][3]);
            } else {
                *(uint32_t*)(Ch + o0) = h2pack(acc[mf][nf][0], acc[mf][nf][1]);
                *(uint32_t*)(Ch + o0 + 8 * DM) = h2pack(acc[mf][nf][2], acc[mf][nf][3]);
            }
        }
    }
}

__global__ void __launch_bounds__(128, 2)
hgemm_qkv(const __half* __restrict__ A, const __half* __restrict__ Wall,
          __half* __restrict__ q, __half* __restrict__ k, __half* __restrict__ v)
{
    extern __shared__ char smraw[];
    GRID_TRIGGER();
    GRID_WAIT();
    const int wsel = blockIdx.x >> 3;
    const int n0 = (blockIdx.x & 7) * 128;
    const int m0 = blockIdx.y * 128;
    const __half* W = Wall + (size_t)wsel * DM * DM;
    __half* Ch = (wsel == 0) ? q : (wsel == 1) ? k : v;
    hgemm_body<1, 0>(A, W, nullptr, Ch, m0, n0, smem_u32(smraw));
}

__global__ void __launch_bounds__(128, 2)
hgemm_o(const __half* __restrict__ A, const __half* __restrict__ W,
        float* __restrict__ Cf)
{
    extern __shared__ char smraw[];
    hgemm_body<0, 1>(A, W, Cf, nullptr, blockIdx.y * 128, blockIdx.x * 128,
                     smem_u32(smraw));
}

// =================================================================
// FlashAttention-2 style causal ALiBi attention (R9 exact body + PDL).
// smem: Q 16KB + 2 stages x (K 8KB + V 8KB) = 48KB.
// =================================================================
#define AT_Q 128
#define AT_K 64
#define ATT_SMEM (16384 + 32768)

__device__ __forceinline__ void load_kv(uint32_t base,
        const __half* kh, const __half* vh, int b, int h, int kb, int tid)
{
    size_t grow = (size_t)(b * T_ + kb * AT_K) * DM + h * HD;
#pragma unroll
    for (int t = 0; t < 2; t++) {
        int idx = tid + t * 256;
        int r = idx >> 3;
        int c = idx & 7;
        uint32_t sw = swz(r, c);
        size_t off = grow + (size_t)r * DM;
        cp16(base +        sw, (const char*)(kh + off) + c * 16);
        cp16(base + 8192 + sw, (const char*)(vh + off) + c * 16);
    }
}

__global__ void __launch_bounds__(256)
attn_mma(const __half* __restrict__ qh, const __half* __restrict__ kh,
         const __half* __restrict__ vh, __half* __restrict__ oh)
{
    extern __shared__ char smraw[];
    GRID_TRIGGER();
    GRID_WAIT();
    const uint32_t sb = smem_u32(smraw);
    const int tid = threadIdx.x, w = tid >> 5, lane = tid & 31;
    const int h = blockIdx.y, b = blockIdx.z;
    const int i0 = (gridDim.x - 1 - blockIdx.x) * AT_Q;
    const int lrow = lane & 15, lsel = lane >> 4;
    const int rq = lane >> 2, c2 = (lane & 3) * 2;
    const int irow_base = i0 + w * 16;
    const int irow = irow_base + rq;

    const float slope  = ex2(-0.5f * (float)(h + 1));
    const float slope2 = slope * 1.4426950408889634f;
    const float scale2 = 0.18033688011112042f;

    const uint32_t sQ = sb;
    auto stgK = [&](int s) { return sb + 16384 + s * 16384; };

    {
        const char* gq = (const char*)(qh + (size_t)(b * T_ + i0) * DM + h * HD);
#pragma unroll
        for (int t = 0; t < 4; t++) {
            int idx = tid + t * 256;
            int r = idx >> 3;
            int c = idx & 7;
            cp16(sQ + swz(r, c), gq + (size_t)r * DM * 2 + c * 16);
        }
        load_kv(stgK(0), kh, vh, b, h, 0, tid);
        CP_COMMIT();
    }

    uint32_t qf[4][4];
    float O[8][4];
#pragma unroll
    for (int i = 0; i < 8; i++)
#pragma unroll
        for (int e = 0; e < 4; e++) O[i][e] = 0.f;
    float m0 = -1e30f, m1 = -1e30f, l0 = 0.f, l1 = 0.f;

    const int NB = (i0 + AT_Q) / AT_K;

    for (int kb = 0; kb < NB; kb++) {
        int s = kb & 1;
        if (kb + 1 < NB) {
            load_kv(stgK(s ^ 1), kh, vh, b, h, kb + 1, tid);
            CP_COMMIT();
            asm volatile("cp.async.wait_group 1;");
        } else {
            asm volatile("cp.async.wait_group 0;");
        }
        __syncthreads();

        if (kb == 0) {
#pragma unroll
            for (int ks = 0; ks < 4; ks++) {
                int r = w * 16 + lrow;
                uint32_t off = (uint32_t)(r * 128 + (((2 * ks + lsel) ^ (r & 7)) << 4));
                ldsm4(qf[ks], sQ + off);
            }
        }

        if (kb * AT_K <= irow_base + 15) {
            const uint32_t sK = stgK(s), sV = sK + 8192;

            float S[8][4];
#pragma unroll
            for (int i = 0; i < 8; i++)
#pragma unroll
                for (int e = 0; e < 4; e++) S[i][e] = 0.f;

#pragma unroll
            for (int ks = 0; ks < 4; ks++) {
#pragma unroll
                for (int np = 0; np < 4; np++) {
                    int r = np * 16 + lrow;
                    uint32_t off = (uint32_t)(r * 128 + (((2 * ks + lsel) ^ (r & 7)) << 4));
                    uint32_t bh[4];
                    ldsm4(bh, sK + off);
                    mma_f16(S[2 * np],     qf[ks], bh[0], bh[2]);
                    mma_f16(S[2 * np + 1], qf[ks], bh[1], bh[3]);
                }
            }

            const int jb = kb * AT_K + c2;
            const bool nomask = (kb * AT_K + 63) <= irow_base;
            float rm0 = -1e30f, rm1 = -1e30f;
#pragma unroll
            for (int nf = 0; nf < 8; nf++) {
                int d0 = irow - (jb + 8 * nf);
                float fd = (float)d0;
                float bia = -slope2 * fd;
                float t0 = fmaf(S[nf][0], scale2, bia);
                float t1 = fmaf(S[nf][1], scale2, bia + slope2);
                float t2 = fmaf(S[nf][2], scale2, bia - 8.f * slope2);
                float t3 = fmaf(S[nf][3], scale2, bia - 7.f * slope2);
                if (!nomask) {
                    t0 = (d0 >= 0)  ? t0 : -1e30f;
                    t1 = (d0 >= 1)  ? t1 : -1e30f;
                    t2 = (d0 >= -8) ? t2 : -1e30f;
                    t3 = (d0 >= -7) ? t3 : -1e30f;
                }
                S[nf][0] = t0; S[nf][1] = t1; S[nf][2] = t2; S[nf][3] = t3;
                rm0 = fmaxf(rm0, fmaxf(t0, t1));
                rm1 = fmaxf(rm1, fmaxf(t2, t3));
            }
            rm0 = fmaxf(rm0, __shfl_xor_sync(0xffffffffu, rm0, 1));
            rm0 = fmaxf(rm0, __shfl_xor_sync(0xffffffffu, rm0, 2));
            rm1 = fmaxf(rm1, __shfl_xor_sync(0xffffffffu, rm1, 1));
            rm1 = fmaxf(rm1, __shfl_xor_sync(0xffffffffu, rm1, 2));

            float m0n = fmaxf(m0, rm0), m1n = fmaxf(m1, rm1);
            float cr0 = ex2(m0 - m0n), cr1 = ex2(m1 - m1n);
            m0 = m0n; m1 = m1n;
            l0 *= cr0; l1 *= cr1;
#pragma unroll
            for (int nf = 0; nf < 8; nf++) {
                O[nf][0] *= cr0; O[nf][1] *= cr0;
                O[nf][2] *= cr1; O[nf][3] *= cr1;
            }
#pragma unroll
            for (int nf = 0; nf < 8; nf++) {
                float p0 = ex2(S[nf][0] - m0);
                float p1 = ex2(S[nf][1] - m0);
                float p2 = ex2(S[nf][2] - m1);
                float p3 = ex2(S[nf][3] - m1);
                S[nf][0] = p0; S[nf][1] = p1; S[nf][2] = p2; S[nf][3] = p3;
                l0 += p0 + p1;
                l1 += p2 + p3;
            }

#pragma unroll
            for (int ks2 = 0; ks2 < 4; ks2++) {
                uint32_t af2[4];
                af2[0] = h2pack(S[2 * ks2][0],     S[2 * ks2][1]);
                af2[1] = h2pack(S[2 * ks2][2],     S[2 * ks2][3]);
                af2[2] = h2pack(S[2 * ks2 + 1][0], S[2 * ks2 + 1][1]);
                af2[3] = h2pack(S[2 * ks2 + 1][2], S[2 * ks2 + 1][3]);
#pragma unroll
                for (int nf2 = 0; nf2 < 4; nf2++) {
                    int r = ks2 * 16 + lrow;
                    uint32_t off = (uint32_t)(r * 128 + (((2 * nf2 + lsel) ^ (r & 7)) << 4));
                    uint32_t bh[4];
                    ldsm4t(bh, sV + off);
                    mma_f16(O[2 * nf2],     af2, bh[0], bh[1]);
                    mma_f16(O[2 * nf2 + 1], af2, bh[2], bh[3]);
                }
            }
        }
        __syncthreads();
    }

    l0 += __shfl_xor_sync(0xffffffffu, l0, 1);
    l0 += __shfl_xor_sync(0xffffffffu, l0, 2);
    l1 += __shfl_xor_sync(0xffffffffu, l1, 1);
    l1 += __shfl_xor_sync(0xffffffffu, l1, 2);
    float iv0 = 1.0f / l0, iv1 = 1.0f / l1;

    size_t obase = (size_t)(b * T_ + irow) * DM + h * HD + c2;
#pragma unroll
    for (int nf = 0; nf < 8; nf++) {
        *(uint32_t*)(oh + obase + 8 * nf) =
            h2pack(O[nf][0] * iv0, O[nf][1] * iv0);
        *(uint32_t*)(oh + obase + 8 * DM + 8 * nf) =
            h2pack(O[nf][2] * iv1, O[nf][3] * iv1);
    }
}

// =================================================================
extern "C" void kernel_launch(void* const* d_in, const int* in_sizes, int n_in,
                              void* d_out, int out_size)
{
    const float* x  = (const float*)d_in[0];
    const float* Wq = (const float*)d_in[1];
    const float* Wk = (const float*)d_in[2];
    const float* Wv = (const float*)d_in[3];
    const float* Wo = (const float*)d_in[4];
    float* out = (float*)d_out;

    __half *xh, *wh, *qh, *kh, *vh, *ah;
    cudaGetSymbolAddress((void**)&xh, g_xh);
    cudaGetSymbolAddress((void**)&wh, g_wh);
    cudaGetSymbolAddress((void**)&qh, g_qh);
    cudaGetSymbolAddress((void**)&kh, g_kh);
    cudaGetSymbolAddress((void**)&vh, g_vh);
    cudaGetSymbolAddress((void**)&ah, g_ah);

    cudaFuncSetAttribute(hgemm_qkv,
                         cudaFuncAttributeMaxDynamicSharedMemorySize, GEMM_SMEM);
    cudaFuncSetAttribute(hgemm_o,
                         cudaFuncAttributeMaxDynamicSharedMemorySize, GEMM_SMEM);
    cudaFuncSetAttribute(attn_mma,
                         cudaFuncAttributeMaxDynamicSharedMemorySize, ATT_SMEM);

    cudaLaunchAttribute pdl[1];
    pdl[0].id = cudaLaunchAttributeProgrammaticStreamSerialization;
    pdl[0].val.programmaticStreamSerializationAllowed = 1;

    // 1) fused converts (MLP=4)
    conv_all<<<CONV_BLOCKS, 256>>>(x, Wq, Wk, Wv, Wo, xh, wh);

    // 2) fused QKV projections
    {
        cudaLaunchConfig_t cfg = {};
        cfg.gridDim = dim3(24, ROWS / 128);
        cfg.blockDim = dim3(128);
        cfg.dynamicSmemBytes = GEMM_SMEM;
        cfg.stream = 0;
        cfg.attrs = pdl;
        cfg.numAttrs = 1;
        cudaLaunchKernelEx(&cfg, hgemm_qkv,
                           (const __half*)xh, (const __half*)wh, qh, kh, vh);
    }

    // 3) attention
    {
        cudaLaunchConfig_t cfg = {};
        cfg.gridDim = dim3(T_ / AT_Q, H_, B_);
        cfg.blockDim = dim3(256);
        cfg.dynamicSmemBytes = ATT_SMEM;
        cfg.stream = 0;
        cfg.attrs = pdl;
        cfg.numAttrs = 1;
        cudaLaunchKernelEx(&cfg, attn_mma,
                           (const __half*)qh, (const __half*)kh,
                           (const __half*)vh, ah);
    }

    // 4) output projection (prefetches Wo before wait)
    {
        cudaLaunchConfig_t cfg = {};
        cfg.gridDim = dim3(DM / 128, ROWS / 128);
        cfg.blockDim = dim3(128);
        cfg.dynamicSmemBytes = GEMM_SMEM;
        cfg.stream = 0;
        cfg.attrs = pdl;
        cfg.numAttrs = 1;
        cudaLaunchKernelEx(&cfg, hgemm_o,
                           (const __half*)ah,
                           (const __half*)(wh + 3 * (size_t)DM * DM), out);
    }
}